// round 1
// baseline (speedup 1.0000x reference)
#include <cuda_runtime.h>
#include <math.h>

#define B_    2
#define N_    2048
#define D_    1024
#define RANK_ 256
#define HEADS_ 16
#define HS_   16
#define DH_   64
#define QKW_  (2*RANK_)     // 512, row width of qk buffer
#define SCALE_ 0.25f        // 1/sqrt(16)

// Scratch (device globals; no allocation allowed)
__device__ float g_qk[B_*N_*QKW_];   // [4096][512]  q = cols [0,256), k = cols [256,512)
__device__ float g_v [B_*N_*D_];     // [4096][1024]

// ----------------------------------------------------------------------------
// C[M,Nn] = A[M,K] @ W[Nn,K]^T   (row-major A, row-major W; classic 128x128x8)
// ----------------------------------------------------------------------------
__global__ __launch_bounds__(256) void gemm_nt(const float* __restrict__ A,
                                               const float* __restrict__ W,
                                               float* __restrict__ C,
                                               int M, int Nn, int K)
{
    const int BM = 128, BN = 128, BK = 8;
    __shared__ float As[BK][BM + 4];
    __shared__ float Bs[BK][BN + 4];

    int tid = threadIdx.x;
    int tx  = tid & 15;          // 0..15 -> 8 cols each
    int ty  = tid >> 4;          // 0..15 -> 8 rows each
    int row0 = blockIdx.y * BM;
    int col0 = blockIdx.x * BN;

    float acc[8][8] = {};

    int lr = tid >> 1;           // 0..127 : tile row to load
    int lk = (tid & 1) * 4;      // 0 or 4 : k-offset within BK
    const float* Aptr = A + (size_t)(row0 + lr) * K + lk;
    const float* Wptr = W + (size_t)(col0 + lr) * K + lk;

    for (int kt = 0; kt < K; kt += BK) {
        float4 av = *(const float4*)(Aptr + kt);
        float4 bv = *(const float4*)(Wptr + kt);
        As[lk+0][lr] = av.x; As[lk+1][lr] = av.y; As[lk+2][lr] = av.z; As[lk+3][lr] = av.w;
        Bs[lk+0][lr] = bv.x; Bs[lk+1][lr] = bv.y; Bs[lk+2][lr] = bv.z; Bs[lk+3][lr] = bv.w;
        __syncthreads();

        #pragma unroll
        for (int kk = 0; kk < BK; kk++) {
            float a[8], b[8];
            #pragma unroll
            for (int i = 0; i < 8; i++) a[i] = As[kk][ty*8 + i];
            #pragma unroll
            for (int j = 0; j < 8; j++) b[j] = Bs[kk][tx*8 + j];
            #pragma unroll
            for (int i = 0; i < 8; i++)
                #pragma unroll
                for (int j = 0; j < 8; j++)
                    acc[i][j] += a[i] * b[j];
        }
        __syncthreads();
    }

    #pragma unroll
    for (int i = 0; i < 8; i++) {
        float* crow = C + (size_t)(row0 + ty*8 + i) * Nn + col0 + tx*8;
        #pragma unroll
        for (int j = 0; j < 8; j += 4) {
            float4 v4 = make_float4(acc[i][j], acc[i][j+1], acc[i][j+2], acc[i][j+3]);
            *(float4*)(crow + j) = v4;
        }
    }
}

// ----------------------------------------------------------------------------
// L2-normalize q (cols 0..255) and k (cols 256..511) over the FULL rank dim.
// One block per row of g_qk, 256 threads.
// ----------------------------------------------------------------------------
__global__ __launch_bounds__(256) void normalize_qk()
{
    float* p = g_qk + (size_t)blockIdx.x * QKW_;
    int t = threadIdx.x;
    float qv = p[t], kv = p[RANK_ + t];
    float qs = qv*qv, ks = kv*kv;
    #pragma unroll
    for (int o = 16; o; o >>= 1) {
        qs += __shfl_xor_sync(0xffffffffu, qs, o);
        ks += __shfl_xor_sync(0xffffffffu, ks, o);
    }
    __shared__ float sq[8], sk[8];
    if ((t & 31) == 0) { sq[t>>5] = qs; sk[t>>5] = ks; }
    __syncthreads();
    float qn = 0.f, kn = 0.f;
    #pragma unroll
    for (int w = 0; w < 8; w++) { qn += sq[w]; kn += sk[w]; }
    p[t]         = qv / fmaxf(sqrtf(qn), 1e-6f);
    p[RANK_ + t] = kv / fmaxf(sqrtf(kn), 1e-6f);
}

// ----------------------------------------------------------------------------
// Causal flash attention. Block = (q-tile of 64, head, batch), 64 threads,
// one thread owns one query row. K tile 64x16 + V tile 64x64 in smem.
// All smem reads in the compute loops are warp-uniform (broadcast).
// ----------------------------------------------------------------------------
__global__ __launch_bounds__(64) void flash_attn(float* __restrict__ out)
{
    __shared__ float Ks[64][HS_];
    __shared__ float Vs[64][DH_];

    int qt = gridDim.x - 1 - blockIdx.x;   // longest blocks first
    int h  = blockIdx.y;
    int b  = blockIdx.z;
    int t  = threadIdx.x;
    int qi = qt * 64 + t;

    // Load & pre-scale this thread's query row
    float q[HS_];
    const float* qrow = g_qk + (size_t)(b*N_ + qi) * QKW_ + h * HS_;
    #pragma unroll
    for (int c = 0; c < HS_; c += 4) {
        float4 f = *(const float4*)(qrow + c);
        q[c]   = f.x * SCALE_; q[c+1] = f.y * SCALE_;
        q[c+2] = f.z * SCALE_; q[c+3] = f.w * SCALE_;
    }

    float m = -1e30f, l = 0.f;
    float acc[DH_];
    #pragma unroll
    for (int d = 0; d < DH_; d++) acc[d] = 0.f;

    for (int kt = 0; kt <= qt; kt++) {
        int kbase = b*N_ + kt*64;
        // K tile: 64x16 floats = 256 float4s, 4 per thread
        #pragma unroll
        for (int it = 0; it < 4; it++) {
            int f4 = t + it*64;
            int r = f4 >> 2, c4 = (f4 & 3) << 2;
            *(float4*)&Ks[r][c4] =
                *(const float4*)(g_qk + (size_t)(kbase + r)*QKW_ + RANK_ + h*HS_ + c4);
        }
        // V tile: 64x64 floats = 1024 float4s, 16 per thread
        #pragma unroll
        for (int it = 0; it < 16; it++) {
            int f4 = t + it*64;
            int r = f4 >> 4, c4 = (f4 & 15) << 2;
            *(float4*)&Vs[r][c4] =
                *(const float4*)(g_v + (size_t)(kbase + r)*D_ + h*DH_ + c4);
        }
        __syncthreads();

        bool diag = (kt == qt);
        float s[64];
        float tmax = -1e30f;
        #pragma unroll
        for (int j = 0; j < 64; j++) {
            float d = 0.f;
            #pragma unroll
            for (int c = 0; c < HS_; c++) d += q[c] * Ks[j][c];
            if (diag && j > t) d = -1e30f;
            s[j] = d;
            tmax = fmaxf(tmax, d);
        }
        float newm = fmaxf(m, tmax);
        float corr = expf(m - newm);
        l *= corr;
        #pragma unroll
        for (int d = 0; d < DH_; d++) acc[d] *= corr;
        #pragma unroll
        for (int j = 0; j < 64; j++) {
            float p = expf(s[j] - newm);
            l += p;
            #pragma unroll
            for (int d = 0; d < DH_; d++) acc[d] += p * Vs[j][d];
        }
        m = newm;
        __syncthreads();
    }

    float inv = 1.f / fmaxf(l, 1e-6f);
    float* orow = out + (size_t)(b*N_ + qi) * D_ + h * DH_;
    #pragma unroll
    for (int d = 0; d < DH_; d += 4) {
        float4 o = make_float4(acc[d]*inv, acc[d+1]*inv, acc[d+2]*inv, acc[d+3]*inv);
        *(float4*)(orow + d) = o;
    }
}

// ----------------------------------------------------------------------------
extern "C" void kernel_launch(void* const* d_in, const int* in_sizes, int n_in,
                              void* d_out, int out_size)
{
    // metadata order: x, mask, Wqk, Wv  (mask is the fixed causal mask; handled analytically)
    const float* x   = (const float*)d_in[0];
    const float* Wqk = (const float*)d_in[2];
    const float* Wv  = (const float*)d_in[3];
    float* out = (float*)d_out;

    float *qk_ptr, *v_ptr;
    cudaGetSymbolAddress((void**)&qk_ptr, g_qk);
    cudaGetSymbolAddress((void**)&v_ptr,  g_v);

    const int M = B_ * N_;   // 4096

    // qk = x @ Wqk^T : [4096, 512]
    gemm_nt<<<dim3(QKW_/128, M/128), 256>>>(x, Wqk, qk_ptr, M, QKW_, D_);
    // v = x @ Wv^T : [4096, 1024]
    gemm_nt<<<dim3(D_/128, M/128), 256>>>(x, Wv, v_ptr, M, D_, D_);
    // normalize q,k rows
    normalize_qk<<<M, 256>>>();
    // causal flash attention -> out
    flash_attn<<<dim3(N_/64, HEADS_, B_), 64>>>(out);
}

// round 3
// speedup vs baseline: 1.7268x; 1.7268x over previous
#include <cuda_runtime.h>
#include <cuda_bf16.h>
#include <cstdint>
#include <math.h>

#define B_    2
#define N_    2048
#define D_    1024
#define RANK_ 256
#define HEADS_ 16
#define HS_   16
#define DH_   64
#define QKW_  512
#define SCALE_ 0.25f
#define MROWS (B_*N_)        // 4096

// ---------------- device scratch (no allocation allowed) --------------------
__device__ float g_qk[MROWS*QKW_];
__device__ float g_v [MROWS*D_];
__device__ __nv_bfloat16 g_xh[MROWS*D_];
__device__ __nv_bfloat16 g_xl[MROWS*D_];
__device__ __nv_bfloat16 g_wh[(QKW_+D_)*D_];
__device__ __nv_bfloat16 g_wl[(QKW_+D_)*D_];

// ---------------- PTX helpers (sm_100-baseline safe) ------------------------
__device__ __forceinline__ uint32_t smem_u32(const void* p) {
    uint32_t a;
    asm("{ .reg .u64 t; cvta.to.shared.u64 t, %1; cvt.u32.u64 %0, t; }" : "=r"(a) : "l"(p));
    return a;
}
__device__ __forceinline__ void cp_async16(uint32_t dst, const void* src) {
    asm volatile("cp.async.cg.shared.global [%0], [%1], 16;" :: "r"(dst), "l"(src) : "memory");
}
#define CP_COMMIT() asm volatile("cp.async.commit_group;" ::: "memory")
#define CP_WAIT(n)  asm volatile("cp.async.wait_group %0;" :: "n"(n) : "memory")

__device__ __forceinline__ void ldsm4(uint32_t* r, uint32_t addr) {
    asm volatile("ldmatrix.sync.aligned.m8n8.x4.shared.b16 {%0,%1,%2,%3}, [%4];"
                 : "=r"(r[0]), "=r"(r[1]), "=r"(r[2]), "=r"(r[3]) : "r"(addr));
}
__device__ __forceinline__ void mma16816(float* d, const uint32_t* a, const uint32_t* b) {
    asm volatile("mma.sync.aligned.m16n8k16.row.col.f32.bf16.bf16.f32 "
                 "{%0,%1,%2,%3}, {%4,%5,%6,%7}, {%8,%9}, {%0,%1,%2,%3};"
                 : "+f"(d[0]), "+f"(d[1]), "+f"(d[2]), "+f"(d[3])
                 : "r"(a[0]), "r"(a[1]), "r"(a[2]), "r"(a[3]), "r"(b[0]), "r"(b[1]));
}

#define FMA2(d, a, b) asm("fma.rn.f32x2 %0, %1, %2, %0;" : "+l"(d) : "l"(a), "l"(b))
#define PACK2(d, lo, hi)  asm("mov.b64 %0, {%1, %2};" : "=l"(d) : "f"(lo), "f"(hi))
#define UNPACK2(lo, hi, s) asm("mov.b64 {%0, %1}, %2;" : "=f"(lo), "=f"(hi) : "l"(s))

// ---------------- fp32 -> bf16 hi/lo conversion -----------------------------
__global__ __launch_bounds__(256) void f32_to_bf16_pair(const float* __restrict__ src,
                                                        __nv_bfloat16* __restrict__ hi,
                                                        __nv_bfloat16* __restrict__ lo) {
    int i = (blockIdx.x * 256 + threadIdx.x) * 4;
    float4 v = *(const float4*)(src + i);
    __nv_bfloat16 h0 = __float2bfloat16_rn(v.x), h1 = __float2bfloat16_rn(v.y);
    __nv_bfloat16 h2 = __float2bfloat16_rn(v.z), h3 = __float2bfloat16_rn(v.w);
    __nv_bfloat16 l0 = __float2bfloat16_rn(v.x - __bfloat162float(h0));
    __nv_bfloat16 l1 = __float2bfloat16_rn(v.y - __bfloat162float(h1));
    __nv_bfloat16 l2 = __float2bfloat16_rn(v.z - __bfloat162float(h2));
    __nv_bfloat16 l3 = __float2bfloat16_rn(v.w - __bfloat162float(h3));
    *(ushort4*)(hi + i) = make_ushort4(__bfloat16_as_ushort(h0), __bfloat16_as_ushort(h1),
                                       __bfloat16_as_ushort(h2), __bfloat16_as_ushort(h3));
    *(ushort4*)(lo + i) = make_ushort4(__bfloat16_as_ushort(l0), __bfloat16_as_ushort(l1),
                                       __bfloat16_as_ushort(l2), __bfloat16_as_ushort(l3));
}

// ---------------- mma.sync bf16 GEMM: C[M,Nn] = A @ W^T ---------------------
// 128x128 tile, BK=32, 8 warps (4M x 2N), each warp 32x64.
// hi/lo split: C = Ah*Bh + Ah*Bl + Al*Bh  (~1e-5 rel err)
#define TILE_PITCH 80                     // bytes per smem row (32 bf16 + 16B pad)
#define TILE_B     (128 * TILE_PITCH)     // 10240 B per tile
#define STAGE_B    (4 * TILE_B)           // Ah,Al,Bh,Bl
#define GEMM_SMEM  (2 * STAGE_B)          // 81920 B

__global__ __launch_bounds__(256) void gemm_tc(const __nv_bfloat16* __restrict__ Ah,
                                               const __nv_bfloat16* __restrict__ Al,
                                               const __nv_bfloat16* __restrict__ Wh,
                                               const __nv_bfloat16* __restrict__ Wl,
                                               float* __restrict__ C, int Nn)
{
    extern __shared__ __align__(128) char smem[];
    const uint32_t sb = smem_u32(smem);

    const int tid = threadIdx.x;
    const int lane = tid & 31, wid = tid >> 5;
    const int wr = wid >> 1, wc = wid & 1;            // warp 4x2 grid
    const int row0 = blockIdx.y * 128, col0 = blockIdx.x * 128;

    // cp.async geometry: per tile, thread handles rows {tid>>2, 64+(tid>>2)}, chunk c=tid&3
    const int lrow0 = tid >> 2, lc = tid & 3;
    const __nv_bfloat16* srcp[4] = {
        Ah + (size_t)row0 * D_, Al + (size_t)row0 * D_,
        Wh + (size_t)col0 * D_, Wl + (size_t)col0 * D_ };

    auto load_stage = [&](int s, int k0) {
        uint32_t dbase = sb + s * STAGE_B;
        #pragma unroll
        for (int t = 0; t < 4; t++) {
            #pragma unroll
            for (int j = 0; j < 2; j++) {
                int row = j * 64 + lrow0;
                cp_async16(dbase + t * TILE_B + row * TILE_PITCH + lc * 16,
                           srcp[t] + (size_t)row * D_ + k0 + lc * 8);
            }
        }
        CP_COMMIT();
    };

    // ldmatrix lane offsets (tile-relative bytes)
    const uint32_t a_off = (uint32_t)((wr * 32 + (lane & 15)) * TILE_PITCH + ((lane >> 4) << 4));
    const uint32_t b_off = (uint32_t)((wc * 64 + (lane & 7) + ((lane >> 4) << 3)) * TILE_PITCH
                                      + (((lane >> 3) & 1) << 4));

    float acc[2][8][4];
    #pragma unroll
    for (int mt = 0; mt < 2; mt++)
        #pragma unroll
        for (int nt = 0; nt < 8; nt++)
            #pragma unroll
            for (int r = 0; r < 4; r++) acc[mt][nt][r] = 0.f;

    load_stage(0, 0);

    const int NK = D_ / 32;   // 32 chunks
    for (int kt = 0; kt < NK; kt++) {
        if (kt + 1 < NK) { load_stage((kt + 1) & 1, (kt + 1) * 32); CP_WAIT(1); }
        else             { CP_WAIT(0); }
        __syncthreads();

        uint32_t stage = sb + (kt & 1) * STAGE_B;
        #pragma unroll
        for (int kk = 0; kk < 2; kk++) {
            uint32_t ko = kk * 32;
            uint32_t ah[2][4], al[2][4];
            #pragma unroll
            for (int mt = 0; mt < 2; mt++) {
                ldsm4(ah[mt], stage + 0 * TILE_B + a_off + mt * (16 * TILE_PITCH) + ko);
                ldsm4(al[mt], stage + 1 * TILE_B + a_off + mt * (16 * TILE_PITCH) + ko);
            }
            uint32_t bh[4][4], bl[4][4];
            #pragma unroll
            for (int ng = 0; ng < 4; ng++) {
                ldsm4(bh[ng], stage + 2 * TILE_B + b_off + ng * (16 * TILE_PITCH) + ko);
                ldsm4(bl[ng], stage + 3 * TILE_B + b_off + ng * (16 * TILE_PITCH) + ko);
            }
            #pragma unroll
            for (int mt = 0; mt < 2; mt++)
                #pragma unroll
                for (int ng = 0; ng < 4; ng++)
                    #pragma unroll
                    for (int hf = 0; hf < 2; hf++) {
                        int nt = ng * 2 + hf;
                        mma16816(acc[mt][nt], ah[mt], &bh[ng][hf * 2]);
                        mma16816(acc[mt][nt], ah[mt], &bl[ng][hf * 2]);
                        mma16816(acc[mt][nt], al[mt], &bh[ng][hf * 2]);
                    }
        }
        __syncthreads();
    }

    // epilogue: m16n8 frag -> C
    #pragma unroll
    for (int mt = 0; mt < 2; mt++) {
        int rbase = row0 + wr * 32 + mt * 16 + (lane >> 2);
        #pragma unroll
        for (int nt = 0; nt < 8; nt++) {
            int col = col0 + wc * 64 + nt * 8 + (lane & 3) * 2;
            float* p0 = C + (size_t)rbase * Nn + col;
            float* p1 = C + (size_t)(rbase + 8) * Nn + col;
            *(float2*)p0 = make_float2(acc[mt][nt][0], acc[mt][nt][1]);
            *(float2*)p1 = make_float2(acc[mt][nt][2], acc[mt][nt][3]);
        }
    }
}

// ---------------- L2 normalize ----------------------------------------------
__global__ __launch_bounds__(256) void normalize_qk()
{
    float* p = g_qk + (size_t)blockIdx.x * QKW_;
    int t = threadIdx.x;
    float qv = p[t], kv = p[RANK_ + t];
    float qs = qv*qv, ks = kv*kv;
    #pragma unroll
    for (int o = 16; o; o >>= 1) {
        qs += __shfl_xor_sync(0xffffffffu, qs, o);
        ks += __shfl_xor_sync(0xffffffffu, ks, o);
    }
    __shared__ float sq[8], sk[8];
    if ((t & 31) == 0) { sq[t>>5] = qs; sk[t>>5] = ks; }
    __syncthreads();
    float qn = 0.f, kn = 0.f;
    #pragma unroll
    for (int w = 0; w < 8; w++) { qn += sq[w]; kn += sk[w]; }
    p[t]         = qv / fmaxf(sqrtf(qn), 1e-6f);
    p[RANK_ + t] = kv / fmaxf(sqrtf(kn), 1e-6f);
}

// ---------------- causal flash attention (no-max softmax, f32x2) ------------
// |score| <= 0.25 (unit-norm q,k, scale 1/4) so exp(s) needs no stabilization.
__global__ __launch_bounds__(64) void flash_attn(float* __restrict__ out)
{
    __shared__ __align__(16) float Ks[64][HS_];
    __shared__ __align__(16) float Vs[64][DH_];

    int qt = gridDim.x - 1 - blockIdx.x;   // longest blocks first
    int h  = blockIdx.y;
    int b  = blockIdx.z;
    int t  = threadIdx.x;
    int qi = qt * 64 + t;

    unsigned long long q2[8];
    const float* qrow = g_qk + (size_t)(b*N_ + qi) * QKW_ + h * HS_;
    #pragma unroll
    for (int c = 0; c < HS_; c += 4) {
        float4 f = *(const float4*)(qrow + c);
        PACK2(q2[c/2],     f.x * SCALE_, f.y * SCALE_);
        PACK2(q2[c/2 + 1], f.z * SCALE_, f.w * SCALE_);
    }

    unsigned long long acc2[32];
    #pragma unroll
    for (int d = 0; d < 32; d++) acc2[d] = 0ull;
    float l = 0.f;

    for (int kt = 0; kt <= qt; kt++) {
        int kbase = b*N_ + kt*64;
        #pragma unroll
        for (int it = 0; it < 4; it++) {
            int f4 = t + it*64;
            int r = f4 >> 2, c4 = (f4 & 3) << 2;
            *(float4*)&Ks[r][c4] =
                *(const float4*)(g_qk + (size_t)(kbase + r)*QKW_ + RANK_ + h*HS_ + c4);
        }
        #pragma unroll
        for (int it = 0; it < 16; it++) {
            int f4 = t + it*64;
            int r = f4 >> 4, c4 = (f4 & 15) << 2;
            *(float4*)&Vs[r][c4] =
                *(const float4*)(g_v + (size_t)(kbase + r)*D_ + h*DH_ + c4);
        }
        __syncthreads();

        int jmax = (kt == qt) ? t : 63;
        #pragma unroll 4
        for (int j = 0; j < 64; j++) {
            const ulonglong2* kp = (const ulonglong2*)&Ks[j][0];
            ulonglong2 ka = kp[0], kb = kp[1], kc = kp[2], kd = kp[3];
            unsigned long long s2 = 0ull;
            FMA2(s2, q2[0], ka.x); FMA2(s2, q2[1], ka.y);
            FMA2(s2, q2[2], kb.x); FMA2(s2, q2[3], kb.y);
            FMA2(s2, q2[4], kc.x); FMA2(s2, q2[5], kc.y);
            FMA2(s2, q2[6], kd.x); FMA2(s2, q2[7], kd.y);
            float slo, shi; UNPACK2(slo, shi, s2);
            float s = slo + shi;
            float pp = (j <= jmax) ? __expf(s) : 0.f;
            l += pp;
            unsigned long long p2; PACK2(p2, pp, pp);
            #pragma unroll
            for (int d = 0; d < 32; d += 2) {
                ulonglong2 v2 = *(const ulonglong2*)&Vs[j][d*2];
                FMA2(acc2[d],   p2, v2.x);
                FMA2(acc2[d+1], p2, v2.y);
            }
        }
        __syncthreads();
    }

    float inv = 1.f / fmaxf(l, 1e-6f);
    float* orow = out + (size_t)(b*N_ + qi) * D_ + h * DH_;
    #pragma unroll
    for (int d = 0; d < 32; d += 2) {
        float a0, a1, a2, a3;
        UNPACK2(a0, a1, acc2[d]);
        UNPACK2(a2, a3, acc2[d+1]);
        *(float4*)(orow + d*2) = make_float4(a0*inv, a1*inv, a2*inv, a3*inv);
    }
}

// ----------------------------------------------------------------------------
extern "C" void kernel_launch(void* const* d_in, const int* in_sizes, int n_in,
                              void* d_out, int out_size)
{
    const float* x   = (const float*)d_in[0];
    const float* Wqk = (const float*)d_in[2];
    const float* Wv  = (const float*)d_in[3];
    float* out = (float*)d_out;

    float *qk_ptr, *v_ptr;
    __nv_bfloat16 *xh, *xl, *wh, *wl;
    cudaGetSymbolAddress((void**)&qk_ptr, g_qk);
    cudaGetSymbolAddress((void**)&v_ptr,  g_v);
    cudaGetSymbolAddress((void**)&xh, g_xh);
    cudaGetSymbolAddress((void**)&xl, g_xl);
    cudaGetSymbolAddress((void**)&wh, g_wh);
    cudaGetSymbolAddress((void**)&wl, g_wl);

    cudaFuncSetAttribute(gemm_tc, cudaFuncAttributeMaxDynamicSharedMemorySize, GEMM_SMEM);

    f32_to_bf16_pair<<<(MROWS*D_)/1024, 256>>>(x, xh, xl);
    f32_to_bf16_pair<<<(QKW_*D_)/1024, 256>>>(Wqk, wh, wl);
    f32_to_bf16_pair<<<(D_*D_)/1024, 256>>>(Wv, wh + (size_t)QKW_*D_, wl + (size_t)QKW_*D_);

    gemm_tc<<<dim3(QKW_/128, MROWS/128), 256, GEMM_SMEM>>>(xh, xl, wh, wl, qk_ptr, QKW_);
    gemm_tc<<<dim3(D_/128, MROWS/128), 256, GEMM_SMEM>>>(xh, xl,
            wh + (size_t)QKW_*D_, wl + (size_t)QKW_*D_, v_ptr, D_);

    normalize_qk<<<MROWS, 256>>>();
    flash_attn<<<dim3(N_/64, HEADS_, B_), 64>>>(out);
}

// round 4
// speedup vs baseline: 3.6101x; 2.0907x over previous
#include <cuda_runtime.h>
#include <cuda_bf16.h>
#include <cstdint>
#include <math.h>

#define B_    2
#define N_    2048
#define D_    1024
#define RANK_ 256
#define HEADS_ 16
#define HS_   16
#define DH_   64
#define QKW_  512
#define SCALE_ 0.25f
#define MROWS (B_*N_)        // 4096

// ---------------- device scratch (no allocation allowed) --------------------
__device__ float g_qk[MROWS*QKW_];
__device__ float g_v [MROWS*D_];
__device__ __nv_bfloat16 g_xh[MROWS*D_];
__device__ __nv_bfloat16 g_xl[MROWS*D_];
__device__ __nv_bfloat16 g_wh[(QKW_+D_)*D_];
__device__ __nv_bfloat16 g_wl[(QKW_+D_)*D_];
__device__ __nv_bfloat16 g_vh[MROWS*D_];
__device__ __nv_bfloat16 g_vl[MROWS*D_];
// q/k in [b,h,n,hs] layout, q pre-scaled by SCALE_
__device__ __nv_bfloat16 g_qh[B_*HEADS_*N_*HS_];
__device__ __nv_bfloat16 g_ql[B_*HEADS_*N_*HS_];
__device__ __nv_bfloat16 g_kh[B_*HEADS_*N_*HS_];
__device__ __nv_bfloat16 g_kl[B_*HEADS_*N_*HS_];

// ---------------- PTX helpers (sm_100-baseline safe) ------------------------
__device__ __forceinline__ uint32_t smem_u32(const void* p) {
    uint32_t a;
    asm("{ .reg .u64 t; cvta.to.shared.u64 t, %1; cvt.u32.u64 %0, t; }" : "=r"(a) : "l"(p));
    return a;
}
__device__ __forceinline__ void cp_async16(uint32_t dst, const void* src) {
    asm volatile("cp.async.cg.shared.global [%0], [%1], 16;" :: "r"(dst), "l"(src) : "memory");
}
#define CP_COMMIT() asm volatile("cp.async.commit_group;" ::: "memory")
#define CP_WAIT(n)  asm volatile("cp.async.wait_group %0;" :: "n"(n) : "memory")

__device__ __forceinline__ void ldsm4(uint32_t* r, uint32_t addr) {
    asm volatile("ldmatrix.sync.aligned.m8n8.x4.shared.b16 {%0,%1,%2,%3}, [%4];"
                 : "=r"(r[0]), "=r"(r[1]), "=r"(r[2]), "=r"(r[3]) : "r"(addr));
}
__device__ __forceinline__ void ldsm4t(uint32_t* r, uint32_t addr) {
    asm volatile("ldmatrix.sync.aligned.m8n8.x4.trans.shared.b16 {%0,%1,%2,%3}, [%4];"
                 : "=r"(r[0]), "=r"(r[1]), "=r"(r[2]), "=r"(r[3]) : "r"(addr));
}
__device__ __forceinline__ void mma16816(float* d, const uint32_t* a, const uint32_t* b) {
    asm volatile("mma.sync.aligned.m16n8k16.row.col.f32.bf16.bf16.f32 "
                 "{%0,%1,%2,%3}, {%4,%5,%6,%7}, {%8,%9}, {%0,%1,%2,%3};"
                 : "+f"(d[0]), "+f"(d[1]), "+f"(d[2]), "+f"(d[3])
                 : "r"(a[0]), "r"(a[1]), "r"(a[2]), "r"(a[3]), "r"(b[0]), "r"(b[1]));
}

// exp(s) for |s| <= 0.25: Taylor-4, rel err < 1e-5
__device__ __forceinline__ float exp_poly(float s) {
    float p = fmaf(s, 1.f/24.f, 1.f/6.f);
    p = fmaf(s, p, 0.5f);
    p = fmaf(s, p, 1.f);
    p = fmaf(s, p, 1.f);
    return p;
}

// ---------------- fp32 -> bf16 hi/lo conversion -----------------------------
__global__ __launch_bounds__(256) void f32_to_bf16_pair(const float* __restrict__ src,
                                                        __nv_bfloat16* __restrict__ hi,
                                                        __nv_bfloat16* __restrict__ lo) {
    int i = (blockIdx.x * 256 + threadIdx.x) * 4;
    float4 v = *(const float4*)(src + i);
    __nv_bfloat16 h0 = __float2bfloat16_rn(v.x), h1 = __float2bfloat16_rn(v.y);
    __nv_bfloat16 h2 = __float2bfloat16_rn(v.z), h3 = __float2bfloat16_rn(v.w);
    __nv_bfloat16 l0 = __float2bfloat16_rn(v.x - __bfloat162float(h0));
    __nv_bfloat16 l1 = __float2bfloat16_rn(v.y - __bfloat162float(h1));
    __nv_bfloat16 l2 = __float2bfloat16_rn(v.z - __bfloat162float(h2));
    __nv_bfloat16 l3 = __float2bfloat16_rn(v.w - __bfloat162float(h3));
    *(ushort4*)(hi + i) = make_ushort4(__bfloat16_as_ushort(h0), __bfloat16_as_ushort(h1),
                                       __bfloat16_as_ushort(h2), __bfloat16_as_ushort(h3));
    *(ushort4*)(lo + i) = make_ushort4(__bfloat16_as_ushort(l0), __bfloat16_as_ushort(l1),
                                       __bfloat16_as_ushort(l2), __bfloat16_as_ushort(l3));
}

// ---------------- mma.sync bf16 GEMM: C[M,Nn] = A @ W^T ---------------------
#define TILE_PITCH 80
#define TILE_B     (128 * TILE_PITCH)
#define STAGE_B    (4 * TILE_B)
#define GEMM_SMEM  (2 * STAGE_B)

__global__ __launch_bounds__(256) void gemm_tc(const __nv_bfloat16* __restrict__ Ah,
                                               const __nv_bfloat16* __restrict__ Al,
                                               const __nv_bfloat16* __restrict__ Wh,
                                               const __nv_bfloat16* __restrict__ Wl,
                                               float* __restrict__ C, int Nn)
{
    extern __shared__ __align__(128) char smem[];
    const uint32_t sb = smem_u32(smem);

    const int tid = threadIdx.x;
    const int lane = tid & 31, wid = tid >> 5;
    const int wr = wid >> 1, wc = wid & 1;
    const int row0 = blockIdx.y * 128, col0 = blockIdx.x * 128;

    const int lrow0 = tid >> 2, lc = tid & 3;
    const __nv_bfloat16* srcp[4] = {
        Ah + (size_t)row0 * D_, Al + (size_t)row0 * D_,
        Wh + (size_t)col0 * D_, Wl + (size_t)col0 * D_ };

    auto load_stage = [&](int s, int k0) {
        uint32_t dbase = sb + s * STAGE_B;
        #pragma unroll
        for (int t = 0; t < 4; t++) {
            #pragma unroll
            for (int j = 0; j < 2; j++) {
                int row = j * 64 + lrow0;
                cp_async16(dbase + t * TILE_B + row * TILE_PITCH + lc * 16,
                           srcp[t] + (size_t)row * D_ + k0 + lc * 8);
            }
        }
        CP_COMMIT();
    };

    const uint32_t a_off = (uint32_t)((wr * 32 + (lane & 15)) * TILE_PITCH + ((lane >> 4) << 4));
    const uint32_t b_off = (uint32_t)((wc * 64 + (lane & 7) + ((lane >> 4) << 3)) * TILE_PITCH
                                      + (((lane >> 3) & 1) << 4));

    float acc[2][8][4];
    #pragma unroll
    for (int mt = 0; mt < 2; mt++)
        #pragma unroll
        for (int nt = 0; nt < 8; nt++)
            #pragma unroll
            for (int r = 0; r < 4; r++) acc[mt][nt][r] = 0.f;

    load_stage(0, 0);

    const int NK = D_ / 32;
    for (int kt = 0; kt < NK; kt++) {
        if (kt + 1 < NK) { load_stage((kt + 1) & 1, (kt + 1) * 32); CP_WAIT(1); }
        else             { CP_WAIT(0); }
        __syncthreads();

        uint32_t stage = sb + (kt & 1) * STAGE_B;
        #pragma unroll
        for (int kk = 0; kk < 2; kk++) {
            uint32_t ko = kk * 32;
            uint32_t ah[2][4], al[2][4];
            #pragma unroll
            for (int mt = 0; mt < 2; mt++) {
                ldsm4(ah[mt], stage + 0 * TILE_B + a_off + mt * (16 * TILE_PITCH) + ko);
                ldsm4(al[mt], stage + 1 * TILE_B + a_off + mt * (16 * TILE_PITCH) + ko);
            }
            uint32_t bh[4][4], bl[4][4];
            #pragma unroll
            for (int ng = 0; ng < 4; ng++) {
                ldsm4(bh[ng], stage + 2 * TILE_B + b_off + ng * (16 * TILE_PITCH) + ko);
                ldsm4(bl[ng], stage + 3 * TILE_B + b_off + ng * (16 * TILE_PITCH) + ko);
            }
            #pragma unroll
            for (int mt = 0; mt < 2; mt++)
                #pragma unroll
                for (int ng = 0; ng < 4; ng++)
                    #pragma unroll
                    for (int hf = 0; hf < 2; hf++) {
                        int nt = ng * 2 + hf;
                        mma16816(acc[mt][nt], ah[mt], &bh[ng][hf * 2]);
                        mma16816(acc[mt][nt], ah[mt], &bl[ng][hf * 2]);
                        mma16816(acc[mt][nt], al[mt], &bh[ng][hf * 2]);
                    }
        }
        __syncthreads();
    }

    #pragma unroll
    for (int mt = 0; mt < 2; mt++) {
        int rbase = row0 + wr * 32 + mt * 16 + (lane >> 2);
        #pragma unroll
        for (int nt = 0; nt < 8; nt++) {
            int col = col0 + wc * 64 + nt * 8 + (lane & 3) * 2;
            float* p0 = C + (size_t)rbase * Nn + col;
            float* p1 = C + (size_t)(rbase + 8) * Nn + col;
            *(float2*)p0 = make_float2(acc[mt][nt][0], acc[mt][nt][1]);
            *(float2*)p1 = make_float2(acc[mt][nt][2], acc[mt][nt][3]);
        }
    }
}

// ---------------- L2 normalize + emit bf16 hi/lo in [b,h,n,hs] --------------
__global__ __launch_bounds__(256) void normalize_qk()
{
    int n = blockIdx.x;                 // 0..4095
    int b = n >> 11, nn = n & 2047;
    const float* p = g_qk + (size_t)n * QKW_;
    int t = threadIdx.x;
    float qv = p[t], kv = p[RANK_ + t];
    float qs = qv*qv, ks = kv*kv;
    #pragma unroll
    for (int o = 16; o; o >>= 1) {
        qs += __shfl_xor_sync(0xffffffffu, qs, o);
        ks += __shfl_xor_sync(0xffffffffu, ks, o);
    }
    __shared__ float sq[8], sk[8];
    if ((t & 31) == 0) { sq[t>>5] = qs; sk[t>>5] = ks; }
    __syncthreads();
    float qn = 0.f, kn = 0.f;
    #pragma unroll
    for (int w = 0; w < 8; w++) { qn += sq[w]; kn += sk[w]; }
    float qo = qv / fmaxf(sqrtf(qn), 1e-6f) * SCALE_;   // fold attention scale into q
    float ko = kv / fmaxf(sqrtf(kn), 1e-6f);

    int h = t >> 4, c = t & 15;
    size_t dst = ((size_t)(b*HEADS_ + h) * N_ + nn) * HS_ + c;
    __nv_bfloat16 qh = __float2bfloat16_rn(qo);
    __nv_bfloat16 kh = __float2bfloat16_rn(ko);
    g_qh[dst] = qh; g_ql[dst] = __float2bfloat16_rn(qo - __bfloat162float(qh));
    g_kh[dst] = kh; g_kl[dst] = __float2bfloat16_rn(ko - __bfloat162float(kh));
}

// ---------------- tensor-core causal flash attention ------------------------
// Block: 128 q-rows x (head, batch). 8 warps, warp w owns rows w*16..w*16+15.
// K tiles of 64 keys, double buffered. All hi/lo 3-term for QK and PV.
#define SQH_  0
#define SQL_  6144
#define SST_  12288
#define STG_  24576
#define SKH_  0
#define SKL_  3072
#define SVH_  6144
#define SVL_  15360
#define FLASH_SMEM 61440    // 12288 + 2*24576

__global__ __launch_bounds__(256) void flash_tc(float* __restrict__ out)
{
    extern __shared__ __align__(128) char smem[];
    const uint32_t sb = smem_u32(smem);
    const int tid = threadIdx.x, lane = tid & 31, wid = tid >> 5;
    const int qt = gridDim.x - 1 - blockIdx.x;         // longest first
    const int h = blockIdx.y, b = blockIdx.z;
    const int q0 = qt * 128;
    const size_t bh = (size_t)(b*HEADS_ + h) * N_;     // q/k row base
    const size_t vb = (size_t)b * N_;                  // v row base

    // ---- Q tiles (hi/lo), pitch 48, loaded once ----
    #pragma unroll
    for (int it = 0; it < 2; it++) {
        int idx = tid + it * 256;                      // 0..511
        int tile = idx >> 8, row = (idx >> 1) & 127, c = idx & 1;
        const __nv_bfloat16* src = (tile ? g_ql : g_qh) + (bh + q0 + row) * HS_ + c * 8;
        cp_async16(sb + (tile ? SQL_ : SQH_) + row * 48 + c * 16, src);
    }
    CP_COMMIT();

    auto load_kv = [&](int s, int ktile) {
        uint32_t st = sb + SST_ + s * STG_;
        int j0 = ktile * 64;
        {   // K hi/lo: 256 chunks, 1 per thread
            int c = tid & 1, row = (tid >> 1) & 63, tile = tid >> 7;
            const __nv_bfloat16* src = (tile ? g_kl : g_kh) + (bh + j0 + row) * HS_ + c * 8;
            cp_async16(st + (tile ? SKL_ : SKH_) + row * 48 + c * 16, src);
        }
        #pragma unroll
        for (int it = 0; it < 4; it++) {   // V hi/lo: 1024 chunks, 4 per thread
            int idx = tid + it * 256;
            int c = idx & 7, row = (idx >> 3) & 63, tile = idx >> 9;
            const __nv_bfloat16* src = (tile ? g_vl : g_vh) + (vb + j0 + row) * D_ + h * DH_ + c * 8;
            cp_async16(st + (tile ? SVL_ : SVH_) + row * 144 + c * 16, src);
        }
        CP_COMMIT();
    };

    load_kv(0, 0);

    uint32_t qah[4], qal[4];
    float yacc[8][4];
    #pragma unroll
    for (int nt = 0; nt < 8; nt++)
        #pragma unroll
        for (int r = 0; r < 4; r++) yacc[nt][r] = 0.f;
    float lsum0 = 0.f, lsum1 = 0.f;

    const int r0g = q0 + wid * 16 + (lane >> 2);
    const int r1g = r0g + 8;
    const int nkt = 2 * qt + 2;

    for (int kt = 0; kt < nkt; kt++) {
        if (kt + 1 < nkt) { load_kv((kt + 1) & 1, kt + 1); CP_WAIT(1); }
        else              { CP_WAIT(0); }
        __syncthreads();

        if (kt == 0) {
            uint32_t qoff = (uint32_t)((wid * 16 + (lane & 15)) * 48 + ((lane >> 4) << 4));
            ldsm4(qah, sb + SQH_ + qoff);
            ldsm4(qal, sb + SQL_ + qoff);
        }

        uint32_t st = sb + SST_ + (kt & 1) * STG_;
        uint32_t pah[4][4], pal[4][4];

        // ---- QK^T + softmax-numerator, per n-tile pair ----
        const uint32_t koff = (uint32_t)((((lane >> 4) << 3) + (lane & 7)) * 48
                                         + (((lane >> 3) & 1) << 4));
        #pragma unroll
        for (int ntp = 0; ntp < 4; ntp++) {
            uint32_t ko = koff + ntp * (16 * 48);
            uint32_t khr[4], klr[4];
            ldsm4(khr, st + SKH_ + ko);
            ldsm4(klr, st + SKL_ + ko);
            float s0[4] = {0,0,0,0}, s1[4] = {0,0,0,0};
            mma16816(s0, qah, &khr[0]);
            mma16816(s0, qah, &klr[0]);
            mma16816(s0, qal, &khr[0]);
            mma16816(s1, qah, &khr[2]);
            mma16816(s1, qah, &klr[2]);
            mma16816(s1, qal, &khr[2]);

            #pragma unroll
            for (int hf = 0; hf < 2; hf++) {
                float* s = hf ? s1 : s0;
                int nt = ntp * 2 + hf;
                int c0 = kt * 64 + nt * 8 + 2 * (lane & 3);
                float p0 = (c0     <= r0g) ? exp_poly(s[0]) : 0.f;
                float p1 = (c0 + 1 <= r0g) ? exp_poly(s[1]) : 0.f;
                float p2 = (c0     <= r1g) ? exp_poly(s[2]) : 0.f;
                float p3 = (c0 + 1 <= r1g) ? exp_poly(s[3]) : 0.f;
                lsum0 += p0 + p1;
                lsum1 += p2 + p3;
                __nv_bfloat16 h0 = __float2bfloat16_rn(p0), h1 = __float2bfloat16_rn(p1);
                __nv_bfloat16 h2 = __float2bfloat16_rn(p2), h3 = __float2bfloat16_rn(p3);
                __nv_bfloat162 hh01 = __halves2bfloat162(h0, h1);
                __nv_bfloat162 hh23 = __halves2bfloat162(h2, h3);
                __nv_bfloat162 ll01 = __halves2bfloat162(
                    __float2bfloat16_rn(p0 - __bfloat162float(h0)),
                    __float2bfloat16_rn(p1 - __bfloat162float(h1)));
                __nv_bfloat162 ll23 = __halves2bfloat162(
                    __float2bfloat16_rn(p2 - __bfloat162float(h2)),
                    __float2bfloat16_rn(p3 - __bfloat162float(h3)));
                int ks = nt >> 1, sl = (nt & 1) * 2;
                pah[ks][sl]     = *(uint32_t*)&hh01;
                pah[ks][sl + 1] = *(uint32_t*)&hh23;
                pal[ks][sl]     = *(uint32_t*)&ll01;
                pal[ks][sl + 1] = *(uint32_t*)&ll23;
            }
        }

        // ---- P @ V ----
        const uint32_t voff = (uint32_t)(((((lane >> 3) & 1) << 3) + (lane & 7)) * 144
                                         + ((lane >> 4) << 4));
        #pragma unroll
        for (int ks = 0; ks < 4; ks++) {
            #pragma unroll
            for (int dnp = 0; dnp < 4; dnp++) {
                uint32_t vo = voff + ks * (16 * 144) + dnp * 32;
                uint32_t vh4[4], vl4[4];
                ldsm4t(vh4, st + SVH_ + vo);
                ldsm4t(vl4, st + SVL_ + vo);
                mma16816(yacc[2*dnp],     pah[ks], &vh4[0]);
                mma16816(yacc[2*dnp],     pah[ks], &vl4[0]);
                mma16816(yacc[2*dnp],     pal[ks], &vh4[0]);
                mma16816(yacc[2*dnp + 1], pah[ks], &vh4[2]);
                mma16816(yacc[2*dnp + 1], pah[ks], &vl4[2]);
                mma16816(yacc[2*dnp + 1], pal[ks], &vh4[2]);
            }
        }
        __syncthreads();
    }

    // ---- softmax denominator (quad reduce) + store ----
    lsum0 += __shfl_xor_sync(0xffffffffu, lsum0, 1);
    lsum0 += __shfl_xor_sync(0xffffffffu, lsum0, 2);
    lsum1 += __shfl_xor_sync(0xffffffffu, lsum1, 1);
    lsum1 += __shfl_xor_sync(0xffffffffu, lsum1, 2);
    float inv0 = 1.f / fmaxf(lsum0, 1e-6f);
    float inv1 = 1.f / fmaxf(lsum1, 1e-6f);

    float* o0 = out + ((size_t)b * N_ + r0g) * D_ + h * DH_ + 2 * (lane & 3);
    #pragma unroll
    for (int nt = 0; nt < 8; nt++) {
        *(float2*)(o0 + nt * 8)           = make_float2(yacc[nt][0] * inv0, yacc[nt][1] * inv0);
        *(float2*)(o0 + nt * 8 + 8 * D_)  = make_float2(yacc[nt][2] * inv1, yacc[nt][3] * inv1);
    }
}

// ----------------------------------------------------------------------------
extern "C" void kernel_launch(void* const* d_in, const int* in_sizes, int n_in,
                              void* d_out, int out_size)
{
    const float* x   = (const float*)d_in[0];
    const float* Wqk = (const float*)d_in[2];
    const float* Wv  = (const float*)d_in[3];
    float* out = (float*)d_out;

    float *qk_ptr, *v_ptr;
    __nv_bfloat16 *xh, *xl, *wh, *wl, *vh, *vl;
    cudaGetSymbolAddress((void**)&qk_ptr, g_qk);
    cudaGetSymbolAddress((void**)&v_ptr,  g_v);
    cudaGetSymbolAddress((void**)&xh, g_xh);
    cudaGetSymbolAddress((void**)&xl, g_xl);
    cudaGetSymbolAddress((void**)&wh, g_wh);
    cudaGetSymbolAddress((void**)&wl, g_wl);
    cudaGetSymbolAddress((void**)&vh, g_vh);
    cudaGetSymbolAddress((void**)&vl, g_vl);

    cudaFuncSetAttribute(gemm_tc,  cudaFuncAttributeMaxDynamicSharedMemorySize, GEMM_SMEM);
    cudaFuncSetAttribute(flash_tc, cudaFuncAttributeMaxDynamicSharedMemorySize, FLASH_SMEM);

    f32_to_bf16_pair<<<(MROWS*D_)/1024, 256>>>(x, xh, xl);
    f32_to_bf16_pair<<<(QKW_*D_)/1024, 256>>>(Wqk, wh, wl);
    f32_to_bf16_pair<<<(D_*D_)/1024, 256>>>(Wv, wh + (size_t)QKW_*D_, wl + (size_t)QKW_*D_);

    gemm_tc<<<dim3(QKW_/128, MROWS/128), 256, GEMM_SMEM>>>(xh, xl, wh, wl, qk_ptr, QKW_);
    gemm_tc<<<dim3(D_/128, MROWS/128), 256, GEMM_SMEM>>>(xh, xl,
            wh + (size_t)QKW_*D_, wl + (size_t)QKW_*D_, v_ptr, D_);

    normalize_qk<<<MROWS, 256>>>();
    f32_to_bf16_pair<<<(MROWS*D_)/1024, 256>>>(v_ptr, vh, vl);

    flash_tc<<<dim3(N_/128, HEADS_, B_), 256, FLASH_SMEM>>>(out);
}

// round 5
// speedup vs baseline: 3.7752x; 1.0457x over previous
#include <cuda_runtime.h>
#include <cuda_bf16.h>
#include <cstdint>
#include <math.h>

#define B_    2
#define N_    2048
#define D_    1024
#define RANK_ 256
#define HEADS_ 16
#define HS_   16
#define DH_   64
#define QKW_  512
#define CW_   1536           // merged GEMM output width (512 qk + 1024 v)
#define SCALE_ 0.25f
#define MROWS (B_*N_)        // 4096

// ---------------- device scratch (no allocation allowed) --------------------
__device__ float g_qk[MROWS*QKW_];
__device__ __nv_bfloat16 g_xh[MROWS*D_];
__device__ __nv_bfloat16 g_xl[MROWS*D_];
__device__ __nv_bfloat16 g_wh[CW_*D_];    // rows 0..511 Wqk, 512..1535 Wv
__device__ __nv_bfloat16 g_wl[CW_*D_];
__device__ __nv_bfloat16 g_vh[MROWS*D_];
__device__ __nv_bfloat16 g_vl[MROWS*D_];
// q/k in [b,h,n,hs] layout, q pre-scaled by SCALE_
__device__ __nv_bfloat16 g_qh[B_*HEADS_*N_*HS_];
__device__ __nv_bfloat16 g_ql[B_*HEADS_*N_*HS_];
__device__ __nv_bfloat16 g_kh[B_*HEADS_*N_*HS_];
__device__ __nv_bfloat16 g_kl[B_*HEADS_*N_*HS_];

// ---------------- PTX helpers (sm_100-baseline safe) ------------------------
__device__ __forceinline__ uint32_t smem_u32(const void* p) {
    uint32_t a;
    asm("{ .reg .u64 t; cvta.to.shared.u64 t, %1; cvt.u32.u64 %0, t; }" : "=r"(a) : "l"(p));
    return a;
}
__device__ __forceinline__ void cp_async16(uint32_t dst, const void* src) {
    asm volatile("cp.async.cg.shared.global [%0], [%1], 16;" :: "r"(dst), "l"(src) : "memory");
}
#define CP_COMMIT() asm volatile("cp.async.commit_group;" ::: "memory")
#define CP_WAIT(n)  asm volatile("cp.async.wait_group %0;" :: "n"(n) : "memory")

__device__ __forceinline__ void ldsm4(uint32_t* r, uint32_t addr) {
    asm volatile("ldmatrix.sync.aligned.m8n8.x4.shared.b16 {%0,%1,%2,%3}, [%4];"
                 : "=r"(r[0]), "=r"(r[1]), "=r"(r[2]), "=r"(r[3]) : "r"(addr));
}
__device__ __forceinline__ void ldsm4t(uint32_t* r, uint32_t addr) {
    asm volatile("ldmatrix.sync.aligned.m8n8.x4.trans.shared.b16 {%0,%1,%2,%3}, [%4];"
                 : "=r"(r[0]), "=r"(r[1]), "=r"(r[2]), "=r"(r[3]) : "r"(addr));
}
__device__ __forceinline__ void mma16816(float* d, const uint32_t* a, const uint32_t* b) {
    asm volatile("mma.sync.aligned.m16n8k16.row.col.f32.bf16.bf16.f32 "
                 "{%0,%1,%2,%3}, {%4,%5,%6,%7}, {%8,%9}, {%0,%1,%2,%3};"
                 : "+f"(d[0]), "+f"(d[1]), "+f"(d[2]), "+f"(d[3])
                 : "r"(a[0]), "r"(a[1]), "r"(a[2]), "r"(a[3]), "r"(b[0]), "r"(b[1]));
}
// packed f32x2 -> bf16x2 (lo in low half)
#define CVT2PK(d, lo, hi) asm("cvt.rn.bf16x2.f32 %0, %1, %2;" : "=r"(d) : "f"(hi), "f"(lo))
__device__ __forceinline__ float bf_lo_f(uint32_t p) { return __uint_as_float(p << 16); }
__device__ __forceinline__ float bf_hi_f(uint32_t p) { return __uint_as_float(p & 0xffff0000u); }

// exp(s) for |s| <= 0.25: Taylor-4, rel err < 1e-5
__device__ __forceinline__ float exp_poly(float s) {
    float p = fmaf(s, 1.f/24.f, 1.f/6.f);
    p = fmaf(s, p, 0.5f);
    p = fmaf(s, p, 1.f);
    p = fmaf(s, p, 1.f);
    return p;
}

// ---------------- fp32 -> bf16 hi/lo conversion -----------------------------
__global__ __launch_bounds__(256) void f32_to_bf16_pair(const float* __restrict__ src,
                                                        __nv_bfloat16* __restrict__ hi,
                                                        __nv_bfloat16* __restrict__ lo) {
    int i = (blockIdx.x * 256 + threadIdx.x) * 4;
    float4 v = *(const float4*)(src + i);
    uint32_t h01, h23;
    CVT2PK(h01, v.x, v.y);
    CVT2PK(h23, v.z, v.w);
    float r0 = v.x - bf_lo_f(h01), r1 = v.y - bf_hi_f(h01);
    float r2 = v.z - bf_lo_f(h23), r3 = v.w - bf_hi_f(h23);
    uint32_t l01, l23;
    CVT2PK(l01, r0, r1);
    CVT2PK(l23, r2, r3);
    *(uint2*)(hi + i) = make_uint2(h01, h23);
    *(uint2*)(lo + i) = make_uint2(l01, l23);
}

// ---------------- merged mma.sync bf16 GEMM ---------------------------------
// C[4096,1536] = x @ [Wqk;Wv]^T.  cols <512 -> g_qk fp32; cols >=512 -> g_vh/g_vl bf16.
// 128x128 tile, BK=32, 8 warps (4Mx2N), hi/lo 3-term.
#define TILE_PITCH 80
#define TILE_B     (128 * TILE_PITCH)
#define STAGE_B    (4 * TILE_B)
#define GEMM_SMEM  (2 * STAGE_B)        // 81920

__global__ __launch_bounds__(256, 2) void gemm_fused(const __nv_bfloat16* __restrict__ Ah,
                                                     const __nv_bfloat16* __restrict__ Al,
                                                     const __nv_bfloat16* __restrict__ Wh,
                                                     const __nv_bfloat16* __restrict__ Wl)
{
    extern __shared__ __align__(128) char smem[];
    const uint32_t sb = smem_u32(smem);

    const int tid = threadIdx.x;
    const int lane = tid & 31, wid = tid >> 5;
    const int wr = wid >> 1, wc = wid & 1;
    const int row0 = blockIdx.y * 128, col0 = blockIdx.x * 128;

    const int lrow0 = tid >> 2, lc = tid & 3;
    const __nv_bfloat16* srcp[4] = {
        Ah + (size_t)row0 * D_, Al + (size_t)row0 * D_,
        Wh + (size_t)col0 * D_, Wl + (size_t)col0 * D_ };

    auto load_stage = [&](int s, int k0) {
        uint32_t dbase = sb + s * STAGE_B;
        #pragma unroll
        for (int t = 0; t < 4; t++) {
            #pragma unroll
            for (int j = 0; j < 2; j++) {
                int row = j * 64 + lrow0;
                cp_async16(dbase + t * TILE_B + row * TILE_PITCH + lc * 16,
                           srcp[t] + (size_t)row * D_ + k0 + lc * 8);
            }
        }
        CP_COMMIT();
    };

    const uint32_t a_off = (uint32_t)((wr * 32 + (lane & 15)) * TILE_PITCH + ((lane >> 4) << 4));
    const uint32_t b_off = (uint32_t)((wc * 64 + (lane & 7) + ((lane >> 4) << 3)) * TILE_PITCH
                                      + (((lane >> 3) & 1) << 4));

    float acc[2][8][4];
    #pragma unroll
    for (int mt = 0; mt < 2; mt++)
        #pragma unroll
        for (int nt = 0; nt < 8; nt++)
            #pragma unroll
            for (int r = 0; r < 4; r++) acc[mt][nt][r] = 0.f;

    load_stage(0, 0);

    const int NK = D_ / 32;
    for (int kt = 0; kt < NK; kt++) {
        if (kt + 1 < NK) { load_stage((kt + 1) & 1, (kt + 1) * 32); CP_WAIT(1); }
        else             { CP_WAIT(0); }
        __syncthreads();

        uint32_t stage = sb + (kt & 1) * STAGE_B;
        #pragma unroll
        for (int kk = 0; kk < 2; kk++) {
            uint32_t ko = kk * 32;
            uint32_t ah[2][4], al[2][4];
            #pragma unroll
            for (int mt = 0; mt < 2; mt++) {
                ldsm4(ah[mt], stage + 0 * TILE_B + a_off + mt * (16 * TILE_PITCH) + ko);
                ldsm4(al[mt], stage + 1 * TILE_B + a_off + mt * (16 * TILE_PITCH) + ko);
            }
            uint32_t bh[4][4], bl[4][4];
            #pragma unroll
            for (int ng = 0; ng < 4; ng++) {
                ldsm4(bh[ng], stage + 2 * TILE_B + b_off + ng * (16 * TILE_PITCH) + ko);
                ldsm4(bl[ng], stage + 3 * TILE_B + b_off + ng * (16 * TILE_PITCH) + ko);
            }
            #pragma unroll
            for (int mt = 0; mt < 2; mt++)
                #pragma unroll
                for (int ng = 0; ng < 4; ng++)
                    #pragma unroll
                    for (int hf = 0; hf < 2; hf++) {
                        int nt = ng * 2 + hf;
                        mma16816(acc[mt][nt], ah[mt], &bh[ng][hf * 2]);
                        mma16816(acc[mt][nt], ah[mt], &bl[ng][hf * 2]);
                        mma16816(acc[mt][nt], al[mt], &bh[ng][hf * 2]);
                    }
        }
        __syncthreads();
    }

    if (col0 < QKW_) {
        // qk region: fp32 store
        #pragma unroll
        for (int mt = 0; mt < 2; mt++) {
            int rbase = row0 + wr * 32 + mt * 16 + (lane >> 2);
            #pragma unroll
            for (int nt = 0; nt < 8; nt++) {
                int col = col0 + wc * 64 + nt * 8 + (lane & 3) * 2;
                *(float2*)(g_qk + (size_t)rbase * QKW_ + col) =
                    make_float2(acc[mt][nt][0], acc[mt][nt][1]);
                *(float2*)(g_qk + (size_t)(rbase + 8) * QKW_ + col) =
                    make_float2(acc[mt][nt][2], acc[mt][nt][3]);
            }
        }
    } else {
        // v region: convert to bf16 hi/lo pairs directly
        #pragma unroll
        for (int mt = 0; mt < 2; mt++) {
            int rbase = row0 + wr * 32 + mt * 16 + (lane >> 2);
            #pragma unroll
            for (int nt = 0; nt < 8; nt++) {
                int col = col0 - QKW_ + wc * 64 + nt * 8 + (lane & 3) * 2;
                #pragma unroll
                for (int half = 0; half < 2; half++) {
                    float a0 = acc[mt][nt][half * 2], a1 = acc[mt][nt][half * 2 + 1];
                    uint32_t hp, lp;
                    CVT2PK(hp, a0, a1);
                    float r0 = a0 - bf_lo_f(hp), r1 = a1 - bf_hi_f(hp);
                    CVT2PK(lp, r0, r1);
                    size_t off = (size_t)(rbase + half * 8) * D_ + col;
                    *(uint32_t*)(g_vh + off) = hp;
                    *(uint32_t*)(g_vl + off) = lp;
                }
            }
        }
    }
}

// ---------------- L2 normalize + emit bf16 hi/lo in [b,h,n,hs] --------------
__global__ __launch_bounds__(256) void normalize_qk()
{
    int n = blockIdx.x;
    int b = n >> 11, nn = n & 2047;
    const float* p = g_qk + (size_t)n * QKW_;
    int t = threadIdx.x;
    float qv = p[t], kv = p[RANK_ + t];
    float qs = qv*qv, ks = kv*kv;
    #pragma unroll
    for (int o = 16; o; o >>= 1) {
        qs += __shfl_xor_sync(0xffffffffu, qs, o);
        ks += __shfl_xor_sync(0xffffffffu, ks, o);
    }
    __shared__ float sq[8], sk[8];
    if ((t & 31) == 0) { sq[t>>5] = qs; sk[t>>5] = ks; }
    __syncthreads();
    float qn = 0.f, kn = 0.f;
    #pragma unroll
    for (int w = 0; w < 8; w++) { qn += sq[w]; kn += sk[w]; }
    float qo = qv / fmaxf(sqrtf(qn), 1e-6f) * SCALE_;
    float ko = kv / fmaxf(sqrtf(kn), 1e-6f);

    int h = t >> 4, c = t & 15;
    size_t dst = ((size_t)(b*HEADS_ + h) * N_ + nn) * HS_ + c;
    __nv_bfloat16 qh = __float2bfloat16_rn(qo);
    __nv_bfloat16 kh = __float2bfloat16_rn(ko);
    g_qh[dst] = qh; g_ql[dst] = __float2bfloat16_rn(qo - __bfloat162float(qh));
    g_kh[dst] = kh; g_kl[dst] = __float2bfloat16_rn(ko - __bfloat162float(kh));
}

// ---------------- tensor-core causal flash attention ------------------------
#define SQH_  0
#define SQL_  6144
#define SST_  12288
#define STG_  24576
#define SKH_  0
#define SKL_  3072
#define SVH_  6144
#define SVL_  15360
#define FLASH_SMEM 61440

__global__ __launch_bounds__(256, 2) void flash_tc(float* __restrict__ out)
{
    extern __shared__ __align__(128) char smem[];
    const uint32_t sb = smem_u32(smem);
    const int tid = threadIdx.x, lane = tid & 31, wid = tid >> 5;
    const int qt = gridDim.x - 1 - blockIdx.x;
    const int h = blockIdx.y, b = blockIdx.z;
    const int q0 = qt * 128;
    const size_t bh = (size_t)(b*HEADS_ + h) * N_;
    const size_t vb = (size_t)b * N_;

    #pragma unroll
    for (int it = 0; it < 2; it++) {
        int idx = tid + it * 256;
        int tile = idx >> 8, row = (idx >> 1) & 127, c = idx & 1;
        const __nv_bfloat16* src = (tile ? g_ql : g_qh) + (bh + q0 + row) * HS_ + c * 8;
        cp_async16(sb + (tile ? SQL_ : SQH_) + row * 48 + c * 16, src);
    }
    CP_COMMIT();

    auto load_kv = [&](int s, int ktile) {
        uint32_t st = sb + SST_ + s * STG_;
        int j0 = ktile * 64;
        {
            int c = tid & 1, row = (tid >> 1) & 63, tile = tid >> 7;
            const __nv_bfloat16* src = (tile ? g_kl : g_kh) + (bh + j0 + row) * HS_ + c * 8;
            cp_async16(st + (tile ? SKL_ : SKH_) + row * 48 + c * 16, src);
        }
        #pragma unroll
        for (int it = 0; it < 4; it++) {
            int idx = tid + it * 256;
            int c = idx & 7, row = (idx >> 3) & 63, tile = idx >> 9;
            const __nv_bfloat16* src = (tile ? g_vl : g_vh) + (vb + j0 + row) * D_ + h * DH_ + c * 8;
            cp_async16(st + (tile ? SVL_ : SVH_) + row * 144 + c * 16, src);
        }
        CP_COMMIT();
    };

    load_kv(0, 0);

    uint32_t qah[4], qal[4];
    float yacc[8][4];
    #pragma unroll
    for (int nt = 0; nt < 8; nt++)
        #pragma unroll
        for (int r = 0; r < 4; r++) yacc[nt][r] = 0.f;
    float lsum0 = 0.f, lsum1 = 0.f;

    const int r0g = q0 + wid * 16 + (lane >> 2);
    const int r1g = r0g + 8;
    const int nkt = 2 * qt + 2;

    for (int kt = 0; kt < nkt; kt++) {
        if (kt + 1 < nkt) { load_kv((kt + 1) & 1, kt + 1); CP_WAIT(1); }
        else              { CP_WAIT(0); }
        __syncthreads();

        if (kt == 0) {
            uint32_t qoff = (uint32_t)((wid * 16 + (lane & 15)) * 48 + ((lane >> 4) << 4));
            ldsm4(qah, sb + SQH_ + qoff);
            ldsm4(qal, sb + SQL_ + qoff);
        }

        uint32_t st = sb + SST_ + (kt & 1) * STG_;
        uint32_t pah[4][4], pal[4][4];

        const uint32_t koff = (uint32_t)((((lane >> 4) << 3) + (lane & 7)) * 48
                                         + (((lane >> 3) & 1) << 4));
        #pragma unroll
        for (int ntp = 0; ntp < 4; ntp++) {
            uint32_t ko = koff + ntp * (16 * 48);
            uint32_t khr[4], klr[4];
            ldsm4(khr, st + SKH_ + ko);
            ldsm4(klr, st + SKL_ + ko);
            float s0[4] = {0,0,0,0}, s1[4] = {0,0,0,0};
            mma16816(s0, qah, &khr[0]);
            mma16816(s0, qah, &klr[0]);
            mma16816(s0, qal, &khr[0]);
            mma16816(s1, qah, &khr[2]);
            mma16816(s1, qah, &klr[2]);
            mma16816(s1, qal, &khr[2]);

            #pragma unroll
            for (int hf = 0; hf < 2; hf++) {
                float* s = hf ? s1 : s0;
                int nt = ntp * 2 + hf;
                int c0 = kt * 64 + nt * 8 + 2 * (lane & 3);
                float p0 = (c0     <= r0g) ? exp_poly(s[0]) : 0.f;
                float p1 = (c0 + 1 <= r0g) ? exp_poly(s[1]) : 0.f;
                float p2 = (c0     <= r1g) ? exp_poly(s[2]) : 0.f;
                float p3 = (c0 + 1 <= r1g) ? exp_poly(s[3]) : 0.f;
                lsum0 += p0 + p1;
                lsum1 += p2 + p3;
                uint32_t hh01, hh23, ll01, ll23;
                CVT2PK(hh01, p0, p1);
                CVT2PK(hh23, p2, p3);
                float r0 = p0 - bf_lo_f(hh01), r1 = p1 - bf_hi_f(hh01);
                float r2 = p2 - bf_lo_f(hh23), r3 = p3 - bf_hi_f(hh23);
                CVT2PK(ll01, r0, r1);
                CVT2PK(ll23, r2, r3);
                int ks = nt >> 1, sl = (nt & 1) * 2;
                pah[ks][sl]     = hh01;
                pah[ks][sl + 1] = hh23;
                pal[ks][sl]     = ll01;
                pal[ks][sl + 1] = ll23;
            }
        }

        const uint32_t voff = (uint32_t)(((((lane >> 3) & 1) << 3) + (lane & 7)) * 144
                                         + ((lane >> 4) << 4));
        #pragma unroll
        for (int ks = 0; ks < 4; ks++) {
            #pragma unroll
            for (int dnp = 0; dnp < 4; dnp++) {
                uint32_t vo = voff + ks * (16 * 144) + dnp * 32;
                uint32_t vh4[4], vl4[4];
                ldsm4t(vh4, st + SVH_ + vo);
                ldsm4t(vl4, st + SVL_ + vo);
                mma16816(yacc[2*dnp],     pah[ks], &vh4[0]);
                mma16816(yacc[2*dnp],     pah[ks], &vl4[0]);
                mma16816(yacc[2*dnp],     pal[ks], &vh4[0]);
                mma16816(yacc[2*dnp + 1], pah[ks], &vh4[2]);
                mma16816(yacc[2*dnp + 1], pah[ks], &vl4[2]);
                mma16816(yacc[2*dnp + 1], pal[ks], &vh4[2]);
            }
        }
        __syncthreads();
    }

    lsum0 += __shfl_xor_sync(0xffffffffu, lsum0, 1);
    lsum0 += __shfl_xor_sync(0xffffffffu, lsum0, 2);
    lsum1 += __shfl_xor_sync(0xffffffffu, lsum1, 1);
    lsum1 += __shfl_xor_sync(0xffffffffu, lsum1, 2);
    float inv0 = 1.f / fmaxf(lsum0, 1e-6f);
    float inv1 = 1.f / fmaxf(lsum1, 1e-6f);

    float* o0 = out + ((size_t)b * N_ + r0g) * D_ + h * DH_ + 2 * (lane & 3);
    #pragma unroll
    for (int nt = 0; nt < 8; nt++) {
        *(float2*)(o0 + nt * 8)           = make_float2(yacc[nt][0] * inv0, yacc[nt][1] * inv0);
        *(float2*)(o0 + nt * 8 + 8 * D_)  = make_float2(yacc[nt][2] * inv1, yacc[nt][3] * inv1);
    }
}

// ----------------------------------------------------------------------------
extern "C" void kernel_launch(void* const* d_in, const int* in_sizes, int n_in,
                              void* d_out, int out_size)
{
    const float* x   = (const float*)d_in[0];
    const float* Wqk = (const float*)d_in[2];
    const float* Wv  = (const float*)d_in[3];
    float* out = (float*)d_out;

    __nv_bfloat16 *xh, *xl, *wh, *wl;
    cudaGetSymbolAddress((void**)&xh, g_xh);
    cudaGetSymbolAddress((void**)&xl, g_xl);
    cudaGetSymbolAddress((void**)&wh, g_wh);
    cudaGetSymbolAddress((void**)&wl, g_wl);

    cudaFuncSetAttribute(gemm_fused, cudaFuncAttributeMaxDynamicSharedMemorySize, GEMM_SMEM);
    cudaFuncSetAttribute(flash_tc,   cudaFuncAttributeMaxDynamicSharedMemorySize, FLASH_SMEM);

    f32_to_bf16_pair<<<(MROWS*D_)/1024, 256>>>(x, xh, xl);
    f32_to_bf16_pair<<<(QKW_*D_)/1024, 256>>>(Wqk, wh, wl);
    f32_to_bf16_pair<<<(D_*D_)/1024, 256>>>(Wv, wh + (size_t)QKW_*D_, wl + (size_t)QKW_*D_);

    gemm_fused<<<dim3(CW_/128, MROWS/128), 256, GEMM_SMEM>>>(xh, xl, wh, wl);

    normalize_qk<<<MROWS, 256>>>();
    flash_tc<<<dim3(N_/128, HEADS_, B_), 256, FLASH_SMEM>>>(out);
}

// round 6
// speedup vs baseline: 5.2954x; 1.4027x over previous
#include <cuda_runtime.h>
#include <cuda_fp16.h>
#include <cstdint>
#include <math.h>

#define B_    2
#define N_    2048
#define D_    1024
#define RANK_ 256
#define HEADS_ 16
#define HS_   16
#define DH_   64
#define QKW_  512
#define CW_   1536           // merged GEMM output width (512 qk + 1024 v)
#define SCALE_ 0.25f
#define MROWS (B_*N_)        // 4096

// ---------------- device scratch (no allocation allowed) --------------------
__device__ float g_qk[MROWS*QKW_];        // fp32 qk pre-normalization
__device__ __half g_xh[MROWS*D_];         // x hi/lo fp16
__device__ __half g_xl[MROWS*D_];
__device__ __half g_wh[CW_*D_];           // [Wqk;Wv] single fp16
__device__ __half g_vh[MROWS*D_];         // v single fp16
// q hi/lo + k single, [b,h,n,hs] layout, q pre-scaled by SCALE_
__device__ __half g_qh[B_*HEADS_*N_*HS_];
__device__ __half g_ql[B_*HEADS_*N_*HS_];
__device__ __half g_kh[B_*HEADS_*N_*HS_];

// ---------------- PTX helpers (sm_100-baseline safe) ------------------------
__device__ __forceinline__ uint32_t smem_u32(const void* p) {
    uint32_t a;
    asm("{ .reg .u64 t; cvta.to.shared.u64 t, %1; cvt.u32.u64 %0, t; }" : "=r"(a) : "l"(p));
    return a;
}
__device__ __forceinline__ void cp_async16(uint32_t dst, const void* src) {
    asm volatile("cp.async.cg.shared.global [%0], [%1], 16;" :: "r"(dst), "l"(src) : "memory");
}
#define CP_COMMIT() asm volatile("cp.async.commit_group;" ::: "memory")
#define CP_WAIT(n)  asm volatile("cp.async.wait_group %0;" :: "n"(n) : "memory")

__device__ __forceinline__ void ldsm4(uint32_t* r, uint32_t addr) {
    asm volatile("ldmatrix.sync.aligned.m8n8.x4.shared.b16 {%0,%1,%2,%3}, [%4];"
                 : "=r"(r[0]), "=r"(r[1]), "=r"(r[2]), "=r"(r[3]) : "r"(addr));
}
__device__ __forceinline__ void ldsm4t(uint32_t* r, uint32_t addr) {
    asm volatile("ldmatrix.sync.aligned.m8n8.x4.trans.shared.b16 {%0,%1,%2,%3}, [%4];"
                 : "=r"(r[0]), "=r"(r[1]), "=r"(r[2]), "=r"(r[3]) : "r"(addr));
}
__device__ __forceinline__ void mma16816(float* d, const uint32_t* a, const uint32_t* b) {
    asm volatile("mma.sync.aligned.m16n8k16.row.col.f32.f16.f16.f32 "
                 "{%0,%1,%2,%3}, {%4,%5,%6,%7}, {%8,%9}, {%0,%1,%2,%3};"
                 : "+f"(d[0]), "+f"(d[1]), "+f"(d[2]), "+f"(d[3])
                 : "r"(a[0]), "r"(a[1]), "r"(a[2]), "r"(a[3]), "r"(b[0]), "r"(b[1]));
}
// packed f32x2 -> f16x2 (lo arg in low half)
#define CVT2PKH(d, lo, hi) asm("cvt.rn.f16x2.f32 %0, %1, %2;" : "=r"(d) : "f"(hi), "f"(lo))
__device__ __forceinline__ float2 unpk_h2(uint32_t p) {
    __half2 h = *reinterpret_cast<__half2*>(&p);
    return __half22float2(h);    // .x = low half
}

// exp(s) for |s| <= 0.26: Taylor-4, rel err < 1e-5
__device__ __forceinline__ float exp_poly(float s) {
    float p = fmaf(s, 1.f/24.f, 1.f/6.f);
    p = fmaf(s, p, 0.5f);
    p = fmaf(s, p, 1.f);
    p = fmaf(s, p, 1.f);
    return p;
}

// ---------------- fp32 -> fp16 conversions ----------------------------------
__global__ __launch_bounds__(256) void f32_to_f16_pair(const float* __restrict__ src,
                                                       __half* __restrict__ hi,
                                                       __half* __restrict__ lo) {
    int i = (blockIdx.x * 256 + threadIdx.x) * 4;
    float4 v = *(const float4*)(src + i);
    uint32_t h01, h23;
    CVT2PKH(h01, v.x, v.y);
    CVT2PKH(h23, v.z, v.w);
    float2 f01 = unpk_h2(h01), f23 = unpk_h2(h23);
    uint32_t l01, l23;
    CVT2PKH(l01, v.x - f01.x, v.y - f01.y);
    CVT2PKH(l23, v.z - f23.x, v.w - f23.y);
    *(uint2*)(hi + i) = make_uint2(h01, h23);
    *(uint2*)(lo + i) = make_uint2(l01, l23);
}
__global__ __launch_bounds__(256) void f32_to_f16_one(const float* __restrict__ src,
                                                      __half* __restrict__ hi) {
    int i = (blockIdx.x * 256 + threadIdx.x) * 4;
    float4 v = *(const float4*)(src + i);
    uint32_t h01, h23;
    CVT2PKH(h01, v.x, v.y);
    CVT2PKH(h23, v.z, v.w);
    *(uint2*)(hi + i) = make_uint2(h01, h23);
}

// ---------------- merged mma.sync fp16 GEMM ---------------------------------
// C[4096,1536] = (xh+xl) @ Wh^T.  cols <512 -> g_qk fp32; cols >=512 -> g_vh fp16.
// 128x128 tile, BK=32, 8 warps (4Mx2N), 2-product split.
#define TILE_PITCH 80
#define TILE_B     (128 * TILE_PITCH)
#define STAGE_B    (3 * TILE_B)         // Ah, Al, Bh
#define GEMM_SMEM  (2 * STAGE_B)        // 61440

__global__ __launch_bounds__(256, 2) void gemm_fused(const __half* __restrict__ Ah,
                                                     const __half* __restrict__ Al,
                                                     const __half* __restrict__ Wh)
{
    extern __shared__ __align__(128) char smem[];
    const uint32_t sb = smem_u32(smem);

    const int tid = threadIdx.x;
    const int lane = tid & 31, wid = tid >> 5;
    const int wr = wid >> 1, wc = wid & 1;
    const int row0 = blockIdx.y * 128, col0 = blockIdx.x * 128;

    const int lrow0 = tid >> 2, lc = tid & 3;
    const __half* srcp[3] = {
        Ah + (size_t)row0 * D_, Al + (size_t)row0 * D_, Wh + (size_t)col0 * D_ };

    auto load_stage = [&](int s, int k0) {
        uint32_t dbase = sb + s * STAGE_B;
        #pragma unroll
        for (int t = 0; t < 3; t++) {
            #pragma unroll
            for (int j = 0; j < 2; j++) {
                int row = j * 64 + lrow0;
                cp_async16(dbase + t * TILE_B + row * TILE_PITCH + lc * 16,
                           srcp[t] + (size_t)row * D_ + k0 + lc * 8);
            }
        }
        CP_COMMIT();
    };

    const uint32_t a_off = (uint32_t)((wr * 32 + (lane & 15)) * TILE_PITCH + ((lane >> 4) << 4));
    const uint32_t b_off = (uint32_t)((wc * 64 + (lane & 7) + ((lane >> 4) << 3)) * TILE_PITCH
                                      + (((lane >> 3) & 1) << 4));

    float acc[2][8][4];
    #pragma unroll
    for (int mt = 0; mt < 2; mt++)
        #pragma unroll
        for (int nt = 0; nt < 8; nt++)
            #pragma unroll
            for (int r = 0; r < 4; r++) acc[mt][nt][r] = 0.f;

    load_stage(0, 0);

    const int NK = D_ / 32;
    for (int kt = 0; kt < NK; kt++) {
        if (kt + 1 < NK) { load_stage((kt + 1) & 1, (kt + 1) * 32); CP_WAIT(1); }
        else             { CP_WAIT(0); }
        __syncthreads();

        uint32_t stage = sb + (kt & 1) * STAGE_B;
        #pragma unroll
        for (int kk = 0; kk < 2; kk++) {
            uint32_t ko = kk * 32;
            uint32_t ah[2][4], al[2][4];
            #pragma unroll
            for (int mt = 0; mt < 2; mt++) {
                ldsm4(ah[mt], stage + 0 * TILE_B + a_off + mt * (16 * TILE_PITCH) + ko);
                ldsm4(al[mt], stage + 1 * TILE_B + a_off + mt * (16 * TILE_PITCH) + ko);
            }
            uint32_t bh[4][4];
            #pragma unroll
            for (int ng = 0; ng < 4; ng++)
                ldsm4(bh[ng], stage + 2 * TILE_B + b_off + ng * (16 * TILE_PITCH) + ko);
            #pragma unroll
            for (int mt = 0; mt < 2; mt++)
                #pragma unroll
                for (int ng = 0; ng < 4; ng++)
                    #pragma unroll
                    for (int hf = 0; hf < 2; hf++) {
                        int nt = ng * 2 + hf;
                        mma16816(acc[mt][nt], ah[mt], &bh[ng][hf * 2]);
                        mma16816(acc[mt][nt], al[mt], &bh[ng][hf * 2]);
                    }
        }
        __syncthreads();
    }

    if (col0 < QKW_) {
        #pragma unroll
        for (int mt = 0; mt < 2; mt++) {
            int rbase = row0 + wr * 32 + mt * 16 + (lane >> 2);
            #pragma unroll
            for (int nt = 0; nt < 8; nt++) {
                int col = col0 + wc * 64 + nt * 8 + (lane & 3) * 2;
                *(float2*)(g_qk + (size_t)rbase * QKW_ + col) =
                    make_float2(acc[mt][nt][0], acc[mt][nt][1]);
                *(float2*)(g_qk + (size_t)(rbase + 8) * QKW_ + col) =
                    make_float2(acc[mt][nt][2], acc[mt][nt][3]);
            }
        }
    } else {
        #pragma unroll
        for (int mt = 0; mt < 2; mt++) {
            int rbase = row0 + wr * 32 + mt * 16 + (lane >> 2);
            #pragma unroll
            for (int nt = 0; nt < 8; nt++) {
                int col = col0 - QKW_ + wc * 64 + nt * 8 + (lane & 3) * 2;
                uint32_t p0, p1;
                CVT2PKH(p0, acc[mt][nt][0], acc[mt][nt][1]);
                CVT2PKH(p1, acc[mt][nt][2], acc[mt][nt][3]);
                *(uint32_t*)(g_vh + (size_t)rbase * D_ + col)       = p0;
                *(uint32_t*)(g_vh + (size_t)(rbase + 8) * D_ + col) = p1;
            }
        }
    }
}

// ---------------- L2 normalize + emit fp16 q(hi/lo), k ----------------------
__global__ __launch_bounds__(256) void normalize_qk()
{
    int n = blockIdx.x;
    int b = n >> 11, nn = n & 2047;
    const float* p = g_qk + (size_t)n * QKW_;
    int t = threadIdx.x;
    float qv = p[t], kv = p[RANK_ + t];
    float qs = qv*qv, ks = kv*kv;
    #pragma unroll
    for (int o = 16; o; o >>= 1) {
        qs += __shfl_xor_sync(0xffffffffu, qs, o);
        ks += __shfl_xor_sync(0xffffffffu, ks, o);
    }
    __shared__ float sq[8], sk[8];
    if ((t & 31) == 0) { sq[t>>5] = qs; sk[t>>5] = ks; }
    __syncthreads();
    float qn = 0.f, kn = 0.f;
    #pragma unroll
    for (int w = 0; w < 8; w++) { qn += sq[w]; kn += sk[w]; }
    float qo = qv / fmaxf(sqrtf(qn), 1e-6f) * SCALE_;
    float ko = kv / fmaxf(sqrtf(kn), 1e-6f);

    int h = t >> 4, c = t & 15;
    size_t dst = ((size_t)(b*HEADS_ + h) * N_ + nn) * HS_ + c;
    __half qh = __float2half_rn(qo);
    g_qh[dst] = qh;
    g_ql[dst] = __float2half_rn(qo - __half2float(qh));
    g_kh[dst] = __float2half_rn(ko);
}

// ---------------- tensor-core causal flash attention ------------------------
// Q split hi/lo, K single, V single, P split hi/lo. 2-product everywhere.
#define SQH_  0
#define SQL_  6144
#define SST_  12288
#define STG_  12288
#define SKH_  0
#define SVH_  3072
#define FLASH_SMEM 36864    // 12288 + 2*12288

__global__ __launch_bounds__(256, 2) void flash_tc(float* __restrict__ out)
{
    extern __shared__ __align__(128) char smem[];
    const uint32_t sb = smem_u32(smem);
    const int tid = threadIdx.x, lane = tid & 31, wid = tid >> 5;
    const int qt = gridDim.x - 1 - blockIdx.x;
    const int h = blockIdx.y, b = blockIdx.z;
    const int q0 = qt * 128;
    const size_t bh = (size_t)(b*HEADS_ + h) * N_;
    const size_t vb = (size_t)b * N_;

    #pragma unroll
    for (int it = 0; it < 2; it++) {
        int idx = tid + it * 256;
        int tile = idx >> 8, row = (idx >> 1) & 127, c = idx & 1;
        const __half* src = (tile ? g_ql : g_qh) + (bh + q0 + row) * HS_ + c * 8;
        cp_async16(sb + (tile ? SQL_ : SQH_) + row * 48 + c * 16, src);
    }
    CP_COMMIT();

    auto load_kv = [&](int s, int ktile) {
        uint32_t st = sb + SST_ + s * STG_;
        int j0 = ktile * 64;
        if (tid < 128) {   // K: 64 rows x 2 chunks
            int c = tid & 1, row = tid >> 1;
            cp_async16(st + SKH_ + row * 48 + c * 16,
                       g_kh + (bh + j0 + row) * HS_ + c * 8);
        }
        #pragma unroll
        for (int it = 0; it < 2; it++) {   // V: 64 rows x 8 chunks = 512
            int idx = tid + it * 256;
            int c = idx & 7, row = idx >> 3;
            cp_async16(st + SVH_ + row * 144 + c * 16,
                       g_vh + (vb + j0 + row) * D_ + h * DH_ + c * 8);
        }
        CP_COMMIT();
    };

    load_kv(0, 0);

    uint32_t qah[4], qal[4];
    float yacc[8][4];
    #pragma unroll
    for (int nt = 0; nt < 8; nt++)
        #pragma unroll
        for (int r = 0; r < 4; r++) yacc[nt][r] = 0.f;
    float lsum0 = 0.f, lsum1 = 0.f;

    const int r0g = q0 + wid * 16 + (lane >> 2);
    const int r1g = r0g + 8;
    const int nkt = 2 * qt + 2;

    for (int kt = 0; kt < nkt; kt++) {
        if (kt + 1 < nkt) { load_kv((kt + 1) & 1, kt + 1); CP_WAIT(1); }
        else              { CP_WAIT(0); }
        __syncthreads();

        if (kt == 0) {
            uint32_t qoff = (uint32_t)((wid * 16 + (lane & 15)) * 48 + ((lane >> 4) << 4));
            ldsm4(qah, sb + SQH_ + qoff);
            ldsm4(qal, sb + SQL_ + qoff);
        }

        uint32_t st = sb + SST_ + (kt & 1) * STG_;
        uint32_t pah[4][4], pal[4][4];

        const uint32_t koff = (uint32_t)((((lane >> 4) << 3) + (lane & 7)) * 48
                                         + (((lane >> 3) & 1) << 4));
        #pragma unroll
        for (int ntp = 0; ntp < 4; ntp++) {
            uint32_t khr[4];
            ldsm4(khr, st + SKH_ + koff + ntp * (16 * 48));
            float s0[4] = {0,0,0,0}, s1[4] = {0,0,0,0};
            mma16816(s0, qah, &khr[0]);
            mma16816(s0, qal, &khr[0]);
            mma16816(s1, qah, &khr[2]);
            mma16816(s1, qal, &khr[2]);

            #pragma unroll
            for (int hf = 0; hf < 2; hf++) {
                float* s = hf ? s1 : s0;
                int nt = ntp * 2 + hf;
                int c0 = kt * 64 + nt * 8 + 2 * (lane & 3);
                float p0 = (c0     <= r0g) ? exp_poly(s[0]) : 0.f;
                float p1 = (c0 + 1 <= r0g) ? exp_poly(s[1]) : 0.f;
                float p2 = (c0     <= r1g) ? exp_poly(s[2]) : 0.f;
                float p3 = (c0 + 1 <= r1g) ? exp_poly(s[3]) : 0.f;
                lsum0 += p0 + p1;
                lsum1 += p2 + p3;
                uint32_t hh01, hh23, ll01, ll23;
                CVT2PKH(hh01, p0, p1);
                CVT2PKH(hh23, p2, p3);
                float2 f01 = unpk_h2(hh01), f23 = unpk_h2(hh23);
                CVT2PKH(ll01, p0 - f01.x, p1 - f01.y);
                CVT2PKH(ll23, p2 - f23.x, p3 - f23.y);
                int ks = nt >> 1, sl = (nt & 1) * 2;
                pah[ks][sl]     = hh01;
                pah[ks][sl + 1] = hh23;
                pal[ks][sl]     = ll01;
                pal[ks][sl + 1] = ll23;
            }
        }

        const uint32_t voff = (uint32_t)(((((lane >> 3) & 1) << 3) + (lane & 7)) * 144
                                         + ((lane >> 4) << 4));
        #pragma unroll
        for (int ks = 0; ks < 4; ks++) {
            #pragma unroll
            for (int dnp = 0; dnp < 4; dnp++) {
                uint32_t vh4[4];
                ldsm4t(vh4, st + SVH_ + voff + ks * (16 * 144) + dnp * 32);
                mma16816(yacc[2*dnp],     pah[ks], &vh4[0]);
                mma16816(yacc[2*dnp],     pal[ks], &vh4[0]);
                mma16816(yacc[2*dnp + 1], pah[ks], &vh4[2]);
                mma16816(yacc[2*dnp + 1], pal[ks], &vh4[2]);
            }
        }
        __syncthreads();
    }

    lsum0 += __shfl_xor_sync(0xffffffffu, lsum0, 1);
    lsum0 += __shfl_xor_sync(0xffffffffu, lsum0, 2);
    lsum1 += __shfl_xor_sync(0xffffffffu, lsum1, 1);
    lsum1 += __shfl_xor_sync(0xffffffffu, lsum1, 2);
    float inv0 = 1.f / fmaxf(lsum0, 1e-6f);
    float inv1 = 1.f / fmaxf(lsum1, 1e-6f);

    float* o0 = out + ((size_t)b * N_ + r0g) * D_ + h * DH_ + 2 * (lane & 3);
    #pragma unroll
    for (int nt = 0; nt < 8; nt++) {
        *(float2*)(o0 + nt * 8)           = make_float2(yacc[nt][0] * inv0, yacc[nt][1] * inv0);
        *(float2*)(o0 + nt * 8 + 8 * D_)  = make_float2(yacc[nt][2] * inv1, yacc[nt][3] * inv1);
    }
}

// ----------------------------------------------------------------------------
extern "C" void kernel_launch(void* const* d_in, const int* in_sizes, int n_in,
                              void* d_out, int out_size)
{
    const float* x   = (const float*)d_in[0];
    const float* Wqk = (const float*)d_in[2];
    const float* Wv  = (const float*)d_in[3];
    float* out = (float*)d_out;

    __half *xh, *xl, *wh;
    cudaGetSymbolAddress((void**)&xh, g_xh);
    cudaGetSymbolAddress((void**)&xl, g_xl);
    cudaGetSymbolAddress((void**)&wh, g_wh);

    cudaFuncSetAttribute(gemm_fused, cudaFuncAttributeMaxDynamicSharedMemorySize, GEMM_SMEM);
    cudaFuncSetAttribute(flash_tc,   cudaFuncAttributeMaxDynamicSharedMemorySize, FLASH_SMEM);

    f32_to_f16_pair<<<(MROWS*D_)/1024, 256>>>(x, xh, xl);
    f32_to_f16_one<<<(QKW_*D_)/1024, 256>>>(Wqk, wh);
    f32_to_f16_one<<<(D_*D_)/1024, 256>>>(Wv, wh + (size_t)QKW_*D_);

    gemm_fused<<<dim3(CW_/128, MROWS/128), 256, GEMM_SMEM>>>(xh, xl, wh);

    normalize_qk<<<MROWS, 256>>>();
    flash_tc<<<dim3(N_/128, HEADS_, B_), 256, FLASH_SMEM>>>(out);
}

// round 7
// speedup vs baseline: 5.9777x; 1.1288x over previous
#include <cuda_runtime.h>
#include <cuda_fp16.h>
#include <cstdint>
#include <math.h>

#define B_    2
#define N_    2048
#define D_    1024
#define RANK_ 256
#define HEADS_ 16
#define HS_   16
#define DH_   64
#define QKW_  512
#define CW_   1536           // merged GEMM output width (512 qk + 1024 v)
#define NT_   96             // GEMM N-tile
#define SCALE_ 0.25f
#define MROWS (B_*N_)        // 4096

// ---------------- device scratch (no allocation allowed) --------------------
__device__ float g_qk[MROWS*QKW_];        // fp32 qk pre-normalization
__device__ __half g_xh[MROWS*D_];         // x hi/lo fp16
__device__ __half g_xl[MROWS*D_];
__device__ __half g_wh[CW_*D_];           // [Wqk;Wv] single fp16
__device__ __half g_vh[MROWS*D_];         // v single fp16
// q hi/lo + k single, [b,h,n,hs] layout, q pre-scaled by SCALE_
__device__ __half g_qh[B_*HEADS_*N_*HS_];
__device__ __half g_ql[B_*HEADS_*N_*HS_];
__device__ __half g_kh[B_*HEADS_*N_*HS_];

// ---------------- PTX helpers (sm_100-baseline safe) ------------------------
__device__ __forceinline__ uint32_t smem_u32(const void* p) {
    uint32_t a;
    asm("{ .reg .u64 t; cvta.to.shared.u64 t, %1; cvt.u32.u64 %0, t; }" : "=r"(a) : "l"(p));
    return a;
}
__device__ __forceinline__ void cp_async16(uint32_t dst, const void* src) {
    asm volatile("cp.async.cg.shared.global [%0], [%1], 16;" :: "r"(dst), "l"(src) : "memory");
}
#define CP_COMMIT() asm volatile("cp.async.commit_group;" ::: "memory")
#define CP_WAIT(n)  asm volatile("cp.async.wait_group %0;" :: "n"(n) : "memory")

__device__ __forceinline__ void ldsm4(uint32_t* r, uint32_t addr) {
    asm volatile("ldmatrix.sync.aligned.m8n8.x4.shared.b16 {%0,%1,%2,%3}, [%4];"
                 : "=r"(r[0]), "=r"(r[1]), "=r"(r[2]), "=r"(r[3]) : "r"(addr));
}
__device__ __forceinline__ void ldsm4t(uint32_t* r, uint32_t addr) {
    asm volatile("ldmatrix.sync.aligned.m8n8.x4.trans.shared.b16 {%0,%1,%2,%3}, [%4];"
                 : "=r"(r[0]), "=r"(r[1]), "=r"(r[2]), "=r"(r[3]) : "r"(addr));
}
__device__ __forceinline__ void mma16816(float* d, const uint32_t* a, const uint32_t* b) {
    asm volatile("mma.sync.aligned.m16n8k16.row.col.f32.f16.f16.f32 "
                 "{%0,%1,%2,%3}, {%4,%5,%6,%7}, {%8,%9}, {%0,%1,%2,%3};"
                 : "+f"(d[0]), "+f"(d[1]), "+f"(d[2]), "+f"(d[3])
                 : "r"(a[0]), "r"(a[1]), "r"(a[2]), "r"(a[3]), "r"(b[0]), "r"(b[1]));
}
// packed f32x2 -> f16x2 (lo arg in low half)
#define CVT2PKH(d, lo, hi) asm("cvt.rn.f16x2.f32 %0, %1, %2;" : "=r"(d) : "f"(hi), "f"(lo))
__device__ __forceinline__ float2 unpk_h2(uint32_t p) {
    __half2 h = *reinterpret_cast<__half2*>(&p);
    return __half22float2(h);    // .x = low half
}

// exp(s) for |s| <= 0.26: Taylor-4, rel err < 1e-5
__device__ __forceinline__ float exp_poly(float s) {
    float p = fmaf(s, 1.f/24.f, 1.f/6.f);
    p = fmaf(s, p, 0.5f);
    p = fmaf(s, p, 1.f);
    p = fmaf(s, p, 1.f);
    return p;
}

// ---------------- fp32 -> fp16 conversions ----------------------------------
__global__ __launch_bounds__(256) void f32_to_f16_pair(const float* __restrict__ src,
                                                       __half* __restrict__ hi,
                                                       __half* __restrict__ lo) {
    int i = (blockIdx.x * 256 + threadIdx.x) * 4;
    float4 v = *(const float4*)(src + i);
    uint32_t h01, h23;
    CVT2PKH(h01, v.x, v.y);
    CVT2PKH(h23, v.z, v.w);
    float2 f01 = unpk_h2(h01), f23 = unpk_h2(h23);
    uint32_t l01, l23;
    CVT2PKH(l01, v.x - f01.x, v.y - f01.y);
    CVT2PKH(l23, v.z - f23.x, v.w - f23.y);
    *(uint2*)(hi + i) = make_uint2(h01, h23);
    *(uint2*)(lo + i) = make_uint2(l01, l23);
}
__global__ __launch_bounds__(256) void f32_to_f16_one(const float* __restrict__ src,
                                                      __half* __restrict__ hi) {
    int i = (blockIdx.x * 256 + threadIdx.x) * 4;
    float4 v = *(const float4*)(src + i);
    uint32_t h01, h23;
    CVT2PKH(h01, v.x, v.y);
    CVT2PKH(h23, v.z, v.w);
    *(uint2*)(hi + i) = make_uint2(h01, h23);
}

// ---------------- merged mma.sync fp16 GEMM ---------------------------------
// C[4096,1536] = (xh+xl) @ Wh^T.  cols <512 -> g_qk fp32; cols >=512 -> g_vh fp16.
// 128(M) x 96(N) tile, BK=32, 8 warps (4M x 2N, each 32x48), 2-product split.
#define TILE_PITCH 80
#define AT_B   (128 * TILE_PITCH)       // 10240 per A tile
#define BT_B   (NT_ * TILE_PITCH)       // 7680 per B tile
#define T_A0   0
#define T_A1   AT_B
#define T_B0   (2 * AT_B)
#define STAGE_B (2 * AT_B + BT_B)       // 28160
#define GEMM_SMEM (2 * STAGE_B)         // 56320

__global__ __launch_bounds__(256, 2) void gemm_fused(const __half* __restrict__ Ah,
                                                     const __half* __restrict__ Al,
                                                     const __half* __restrict__ Wh)
{
    extern __shared__ __align__(128) char smem[];
    const uint32_t sb = smem_u32(smem);

    const int tid = threadIdx.x;
    const int lane = tid & 31, wid = tid >> 5;
    const int wr = wid >> 1, wc = wid & 1;
    const int row0 = blockIdx.y * 128, col0 = blockIdx.x * NT_;

    const int lrow0 = tid >> 2, lc = tid & 3;
    const __half* pA0 = Ah + (size_t)row0 * D_;
    const __half* pA1 = Al + (size_t)row0 * D_;
    const __half* pB  = Wh + (size_t)col0 * D_;

    auto load_stage = [&](int s, int k0) {
        uint32_t dbase = sb + s * STAGE_B;
        #pragma unroll
        for (int j = 0; j < 2; j++) {
            int row = j * 64 + lrow0;
            cp_async16(dbase + T_A0 + row * TILE_PITCH + lc * 16,
                       pA0 + (size_t)row * D_ + k0 + lc * 8);
            cp_async16(dbase + T_A1 + row * TILE_PITCH + lc * 16,
                       pA1 + (size_t)row * D_ + k0 + lc * 8);
        }
        cp_async16(dbase + T_B0 + lrow0 * TILE_PITCH + lc * 16,
                   pB + (size_t)lrow0 * D_ + k0 + lc * 8);
        if (tid < 128) {
            int row = 64 + lrow0;
            cp_async16(dbase + T_B0 + row * TILE_PITCH + lc * 16,
                       pB + (size_t)row * D_ + k0 + lc * 8);
        }
        CP_COMMIT();
    };

    const uint32_t a_off = (uint32_t)((wr * 32 + (lane & 15)) * TILE_PITCH + ((lane >> 4) << 4));
    const uint32_t b_off = (uint32_t)((wc * 48 + (lane & 7) + ((lane >> 4) << 3)) * TILE_PITCH
                                      + (((lane >> 3) & 1) << 4));

    float acc[2][6][4];
    #pragma unroll
    for (int mt = 0; mt < 2; mt++)
        #pragma unroll
        for (int nt = 0; nt < 6; nt++)
            #pragma unroll
            for (int r = 0; r < 4; r++) acc[mt][nt][r] = 0.f;

    load_stage(0, 0);

    const int NK = D_ / 32;
    for (int kt = 0; kt < NK; kt++) {
        if (kt + 1 < NK) { load_stage((kt + 1) & 1, (kt + 1) * 32); CP_WAIT(1); }
        else             { CP_WAIT(0); }
        __syncthreads();

        uint32_t stage = sb + (kt & 1) * STAGE_B;
        #pragma unroll
        for (int kk = 0; kk < 2; kk++) {
            uint32_t ko = kk * 32;
            uint32_t ah[2][4], al[2][4];
            #pragma unroll
            for (int mt = 0; mt < 2; mt++) {
                ldsm4(ah[mt], stage + T_A0 + a_off + mt * (16 * TILE_PITCH) + ko);
                ldsm4(al[mt], stage + T_A1 + a_off + mt * (16 * TILE_PITCH) + ko);
            }
            uint32_t bh[3][4];
            #pragma unroll
            for (int ng = 0; ng < 3; ng++)
                ldsm4(bh[ng], stage + T_B0 + b_off + ng * (16 * TILE_PITCH) + ko);
            #pragma unroll
            for (int mt = 0; mt < 2; mt++)
                #pragma unroll
                for (int ng = 0; ng < 3; ng++)
                    #pragma unroll
                    for (int hf = 0; hf < 2; hf++) {
                        int nt = ng * 2 + hf;
                        mma16816(acc[mt][nt], ah[mt], &bh[ng][hf * 2]);
                        mma16816(acc[mt][nt], al[mt], &bh[ng][hf * 2]);
                    }
        }
        __syncthreads();
    }

    // epilogue: per-fragment qk(fp32) vs v(fp16) routing; boundary 512 is frag-aligned
    #pragma unroll
    for (int mt = 0; mt < 2; mt++) {
        int rbase = row0 + wr * 32 + mt * 16 + (lane >> 2);
        #pragma unroll
        for (int nt = 0; nt < 6; nt++) {
            int colg = col0 + wc * 48 + nt * 8 + (lane & 3) * 2;
            if (colg < QKW_) {
                *(float2*)(g_qk + (size_t)rbase * QKW_ + colg) =
                    make_float2(acc[mt][nt][0], acc[mt][nt][1]);
                *(float2*)(g_qk + (size_t)(rbase + 8) * QKW_ + colg) =
                    make_float2(acc[mt][nt][2], acc[mt][nt][3]);
            } else {
                int col = colg - QKW_;
                uint32_t p0, p1;
                CVT2PKH(p0, acc[mt][nt][0], acc[mt][nt][1]);
                CVT2PKH(p1, acc[mt][nt][2], acc[mt][nt][3]);
                *(uint32_t*)(g_vh + (size_t)rbase * D_ + col)       = p0;
                *(uint32_t*)(g_vh + (size_t)(rbase + 8) * D_ + col) = p1;
            }
        }
    }
}

// ---------------- L2 normalize + emit fp16 q(hi/lo), k ----------------------
__global__ __launch_bounds__(256) void normalize_qk()
{
    int n = blockIdx.x;
    int b = n >> 11, nn = n & 2047;
    const float* p = g_qk + (size_t)n * QKW_;
    int t = threadIdx.x;
    float qv = p[t], kv = p[RANK_ + t];
    float qs = qv*qv, ks = kv*kv;
    #pragma unroll
    for (int o = 16; o; o >>= 1) {
        qs += __shfl_xor_sync(0xffffffffu, qs, o);
        ks += __shfl_xor_sync(0xffffffffu, ks, o);
    }
    __shared__ float sq[8], sk[8];
    if ((t & 31) == 0) { sq[t>>5] = qs; sk[t>>5] = ks; }
    __syncthreads();
    float qn = 0.f, kn = 0.f;
    #pragma unroll
    for (int w = 0; w < 8; w++) { qn += sq[w]; kn += sk[w]; }
    float qo = qv / fmaxf(sqrtf(qn), 1e-6f) * SCALE_;
    float ko = kv / fmaxf(sqrtf(kn), 1e-6f);

    int h = t >> 4, c = t & 15;
    size_t dst = ((size_t)(b*HEADS_ + h) * N_ + nn) * HS_ + c;
    __half qh = __float2half_rn(qo);
    g_qh[dst] = qh;
    g_ql[dst] = __float2half_rn(qo - __half2float(qh));
    g_kh[dst] = __float2half_rn(ko);
}

// ---------------- tensor-core causal flash attention ------------------------
// Q split hi/lo (2-prod QK), K single, V single, P single fp16.
#define SQH_  0
#define SQL_  6144
#define SST_  12288
#define STG_  12288
#define SKH_  0
#define SVH_  3072
#define FLASH_SMEM 36864    // 12288 + 2*12288

__global__ __launch_bounds__(256, 2) void flash_tc(float* __restrict__ out)
{
    extern __shared__ __align__(128) char smem[];
    const uint32_t sb = smem_u32(smem);
    const int tid = threadIdx.x, lane = tid & 31, wid = tid >> 5;
    const int qt = gridDim.x - 1 - blockIdx.x;
    const int h = blockIdx.y, b = blockIdx.z;
    const int q0 = qt * 128;
    const size_t bh = (size_t)(b*HEADS_ + h) * N_;
    const size_t vb = (size_t)b * N_;

    #pragma unroll
    for (int it = 0; it < 2; it++) {
        int idx = tid + it * 256;
        int tile = idx >> 8, row = (idx >> 1) & 127, c = idx & 1;
        const __half* src = (tile ? g_ql : g_qh) + (bh + q0 + row) * HS_ + c * 8;
        cp_async16(sb + (tile ? SQL_ : SQH_) + row * 48 + c * 16, src);
    }
    CP_COMMIT();

    auto load_kv = [&](int s, int ktile) {
        uint32_t st = sb + SST_ + s * STG_;
        int j0 = ktile * 64;
        if (tid < 128) {   // K: 64 rows x 2 chunks
            int c = tid & 1, row = tid >> 1;
            cp_async16(st + SKH_ + row * 48 + c * 16,
                       g_kh + (bh + j0 + row) * HS_ + c * 8);
        }
        #pragma unroll
        for (int it = 0; it < 2; it++) {   // V: 64 rows x 8 chunks = 512
            int idx = tid + it * 256;
            int c = idx & 7, row = idx >> 3;
            cp_async16(st + SVH_ + row * 144 + c * 16,
                       g_vh + (vb + j0 + row) * D_ + h * DH_ + c * 8);
        }
        CP_COMMIT();
    };

    load_kv(0, 0);

    uint32_t qah[4], qal[4];
    float yacc[8][4];
    #pragma unroll
    for (int nt = 0; nt < 8; nt++)
        #pragma unroll
        for (int r = 0; r < 4; r++) yacc[nt][r] = 0.f;
    float lsum0 = 0.f, lsum1 = 0.f;

    const int r0g = q0 + wid * 16 + (lane >> 2);
    const int r1g = r0g + 8;
    const int nkt = 2 * qt + 2;

    for (int kt = 0; kt < nkt; kt++) {
        if (kt + 1 < nkt) { load_kv((kt + 1) & 1, kt + 1); CP_WAIT(1); }
        else              { CP_WAIT(0); }
        __syncthreads();

        if (kt == 0) {
            uint32_t qoff = (uint32_t)((wid * 16 + (lane & 15)) * 48 + ((lane >> 4) << 4));
            ldsm4(qah, sb + SQH_ + qoff);
            ldsm4(qal, sb + SQL_ + qoff);
        }

        uint32_t st = sb + SST_ + (kt & 1) * STG_;
        uint32_t pah[4][4];

        const uint32_t koff = (uint32_t)((((lane >> 4) << 3) + (lane & 7)) * 48
                                         + (((lane >> 3) & 1) << 4));
        #pragma unroll
        for (int ntp = 0; ntp < 4; ntp++) {
            uint32_t khr[4];
            ldsm4(khr, st + SKH_ + koff + ntp * (16 * 48));
            float s0[4] = {0,0,0,0}, s1[4] = {0,0,0,0};
            mma16816(s0, qah, &khr[0]);
            mma16816(s0, qal, &khr[0]);
            mma16816(s1, qah, &khr[2]);
            mma16816(s1, qal, &khr[2]);

            #pragma unroll
            for (int hf = 0; hf < 2; hf++) {
                float* s = hf ? s1 : s0;
                int nt = ntp * 2 + hf;
                int c0 = kt * 64 + nt * 8 + 2 * (lane & 3);
                float p0 = (c0     <= r0g) ? exp_poly(s[0]) : 0.f;
                float p1 = (c0 + 1 <= r0g) ? exp_poly(s[1]) : 0.f;
                float p2 = (c0     <= r1g) ? exp_poly(s[2]) : 0.f;
                float p3 = (c0 + 1 <= r1g) ? exp_poly(s[3]) : 0.f;
                lsum0 += p0 + p1;
                lsum1 += p2 + p3;
                uint32_t hh01, hh23;
                CVT2PKH(hh01, p0, p1);
                CVT2PKH(hh23, p2, p3);
                int ks = nt >> 1, sl = (nt & 1) * 2;
                pah[ks][sl]     = hh01;
                pah[ks][sl + 1] = hh23;
            }
        }

        const uint32_t voff = (uint32_t)(((((lane >> 3) & 1) << 3) + (lane & 7)) * 144
                                         + ((lane >> 4) << 4));
        #pragma unroll
        for (int ks = 0; ks < 4; ks++) {
            #pragma unroll
            for (int dnp = 0; dnp < 4; dnp++) {
                uint32_t vh4[4];
                ldsm4t(vh4, st + SVH_ + voff + ks * (16 * 144) + dnp * 32);
                mma16816(yacc[2*dnp],     pah[ks], &vh4[0]);
                mma16816(yacc[2*dnp + 1], pah[ks], &vh4[2]);
            }
        }
        __syncthreads();
    }

    lsum0 += __shfl_xor_sync(0xffffffffu, lsum0, 1);
    lsum0 += __shfl_xor_sync(0xffffffffu, lsum0, 2);
    lsum1 += __shfl_xor_sync(0xffffffffu, lsum1, 1);
    lsum1 += __shfl_xor_sync(0xffffffffu, lsum1, 2);
    float inv0 = 1.f / fmaxf(lsum0, 1e-6f);
    float inv1 = 1.f / fmaxf(lsum1, 1e-6f);

    float* o0 = out + ((size_t)b * N_ + r0g) * D_ + h * DH_ + 2 * (lane & 3);
    #pragma unroll
    for (int nt = 0; nt < 8; nt++) {
        *(float2*)(o0 + nt * 8)           = make_float2(yacc[nt][0] * inv0, yacc[nt][1] * inv0);
        *(float2*)(o0 + nt * 8 + 8 * D_)  = make_float2(yacc[nt][2] * inv1, yacc[nt][3] * inv1);
    }
}

// ----------------------------------------------------------------------------
extern "C" void kernel_launch(void* const* d_in, const int* in_sizes, int n_in,
                              void* d_out, int out_size)
{
    const float* x   = (const float*)d_in[0];
    const float* Wqk = (const float*)d_in[2];
    const float* Wv  = (const float*)d_in[3];
    float* out = (float*)d_out;

    __half *xh, *xl, *wh;
    cudaGetSymbolAddress((void**)&xh, g_xh);
    cudaGetSymbolAddress((void**)&xl, g_xl);
    cudaGetSymbolAddress((void**)&wh, g_wh);

    cudaFuncSetAttribute(gemm_fused, cudaFuncAttributeMaxDynamicSharedMemorySize, GEMM_SMEM);
    cudaFuncSetAttribute(flash_tc,   cudaFuncAttributeMaxDynamicSharedMemorySize, FLASH_SMEM);

    f32_to_f16_pair<<<(MROWS*D_)/1024, 256>>>(x, xh, xl);
    f32_to_f16_one<<<(QKW_*D_)/1024, 256>>>(Wqk, wh);
    f32_to_f16_one<<<(D_*D_)/1024, 256>>>(Wv, wh + (size_t)QKW_*D_);

    gemm_fused<<<dim3(CW_/NT_, MROWS/128), 256, GEMM_SMEM>>>(xh, xl, wh);

    normalize_qk<<<MROWS, 256>>>();
    flash_tc<<<dim3(N_/128, HEADS_, B_), 256, FLASH_SMEM>>>(out);
}

// round 8
// speedup vs baseline: 8.3848x; 1.4027x over previous
#include <cuda_runtime.h>
#include <cuda_fp16.h>
#include <cstdint>
#include <math.h>

#define B_    2
#define N_    2048
#define D_    1024
#define RANK_ 256
#define HEADS_ 16
#define HS_   16
#define DH_   64
#define QKW_  512
#define CW_   1536           // merged GEMM output width (512 qk + 1024 v)
#define NT_   96             // GEMM N-tile
#define SCALE_ 0.25f
#define MROWS (B_*N_)        // 4096

// ---------------- device scratch (no allocation allowed) --------------------
__device__ float g_qk[MROWS*QKW_];        // fp32 qk pre-normalization
__device__ __half g_x16[MROWS*D_];        // x fp16
__device__ __half g_wh[CW_*D_];           // [Wqk;Wv] fp16
__device__ __half g_vh[MROWS*D_];         // v fp16
// q (scaled) and k fp16, [b,h,n,hs] layout
__device__ __half g_q16[B_*HEADS_*N_*HS_];
__device__ __half g_k16[B_*HEADS_*N_*HS_];

// ---------------- PTX helpers (sm_100-baseline safe) ------------------------
__device__ __forceinline__ uint32_t smem_u32(const void* p) {
    uint32_t a;
    asm("{ .reg .u64 t; cvta.to.shared.u64 t, %1; cvt.u32.u64 %0, t; }" : "=r"(a) : "l"(p));
    return a;
}
__device__ __forceinline__ void cp_async16(uint32_t dst, const void* src) {
    asm volatile("cp.async.cg.shared.global [%0], [%1], 16;" :: "r"(dst), "l"(src) : "memory");
}
#define CP_COMMIT() asm volatile("cp.async.commit_group;" ::: "memory")
#define CP_WAIT(n)  asm volatile("cp.async.wait_group %0;" :: "n"(n) : "memory")

__device__ __forceinline__ void ldsm4(uint32_t* r, uint32_t addr) {
    asm volatile("ldmatrix.sync.aligned.m8n8.x4.shared.b16 {%0,%1,%2,%3}, [%4];"
                 : "=r"(r[0]), "=r"(r[1]), "=r"(r[2]), "=r"(r[3]) : "r"(addr));
}
__device__ __forceinline__ void ldsm4t(uint32_t* r, uint32_t addr) {
    asm volatile("ldmatrix.sync.aligned.m8n8.x4.trans.shared.b16 {%0,%1,%2,%3}, [%4];"
                 : "=r"(r[0]), "=r"(r[1]), "=r"(r[2]), "=r"(r[3]) : "r"(addr));
}
__device__ __forceinline__ void mma16816(float* d, const uint32_t* a, const uint32_t* b) {
    asm volatile("mma.sync.aligned.m16n8k16.row.col.f32.f16.f16.f32 "
                 "{%0,%1,%2,%3}, {%4,%5,%6,%7}, {%8,%9}, {%0,%1,%2,%3};"
                 : "+f"(d[0]), "+f"(d[1]), "+f"(d[2]), "+f"(d[3])
                 : "r"(a[0]), "r"(a[1]), "r"(a[2]), "r"(a[3]), "r"(b[0]), "r"(b[1]));
}
// packed f32x2 -> f16x2 (lo arg in low half)
#define CVT2PKH(d, lo, hi) asm("cvt.rn.f16x2.f32 %0, %1, %2;" : "=r"(d) : "f"(hi), "f"(lo))

// exp(s) for |s| <= 0.26: Taylor-4, rel err < 1e-5
__device__ __forceinline__ float exp_poly(float s) {
    float p = fmaf(s, 1.f/24.f, 1.f/6.f);
    p = fmaf(s, p, 0.5f);
    p = fmaf(s, p, 1.f);
    p = fmaf(s, p, 1.f);
    return p;
}

// ---------------- fp32 -> fp16 conversion -----------------------------------
__global__ __launch_bounds__(256) void f32_to_f16_one(const float* __restrict__ src,
                                                      __half* __restrict__ hi) {
    int i = (blockIdx.x * 256 + threadIdx.x) * 4;
    float4 v = *(const float4*)(src + i);
    uint32_t h01, h23;
    CVT2PKH(h01, v.x, v.y);
    CVT2PKH(h23, v.z, v.w);
    *(uint2*)(hi + i) = make_uint2(h01, h23);
}

// ---------------- merged mma.sync fp16 GEMM ---------------------------------
// C[4096,1536] = x16 @ Wh^T.  cols <512 -> g_qk fp32; cols >=512 -> g_vh fp16.
// 128(M) x 96(N) tile, BK=64, 8 warps (4M x 2N, each 32x48), single product.
#define TILE_PITCH 144                  // 64 halves + 16B pad
#define AT_B   (128 * TILE_PITCH)       // 18432
#define BT_B   (NT_ * TILE_PITCH)       // 13824
#define T_B0   AT_B
#define STAGE_B (AT_B + BT_B)           // 32256
#define GEMM_SMEM (2 * STAGE_B)         // 64512

__global__ __launch_bounds__(256, 2) void gemm_fused(const __half* __restrict__ A16,
                                                     const __half* __restrict__ Wh)
{
    extern __shared__ __align__(128) char smem[];
    const uint32_t sb = smem_u32(smem);

    const int tid = threadIdx.x;
    const int lane = tid & 31, wid = tid >> 5;
    const int wr = wid >> 1, wc = wid & 1;
    const int row0 = blockIdx.y * 128, col0 = blockIdx.x * NT_;

    const __half* pA = A16 + (size_t)row0 * D_;
    const __half* pB = Wh + (size_t)col0 * D_;
    const int lrow = tid >> 3, lc = tid & 7;     // 32 rows per 256-thread pass

    auto load_stage = [&](int s, int k0) {
        uint32_t dbase = sb + s * STAGE_B;
        #pragma unroll
        for (int it = 0; it < 4; it++) {         // A: 128 rows x 8 chunks
            int row = lrow + it * 32;
            cp_async16(dbase + row * TILE_PITCH + lc * 16,
                       pA + (size_t)row * D_ + k0 + lc * 8);
        }
        #pragma unroll
        for (int it = 0; it < 3; it++) {         // B: 96 rows x 8 chunks
            int row = lrow + it * 32;
            cp_async16(dbase + T_B0 + row * TILE_PITCH + lc * 16,
                       pB + (size_t)row * D_ + k0 + lc * 8);
        }
        CP_COMMIT();
    };

    const uint32_t a_off = (uint32_t)((wr * 32 + (lane & 15)) * TILE_PITCH + ((lane >> 4) << 4));
    const uint32_t b_off = (uint32_t)((wc * 48 + (lane & 7) + ((lane >> 4) << 3)) * TILE_PITCH
                                      + (((lane >> 3) & 1) << 4));

    float acc[2][6][4];
    #pragma unroll
    for (int mt = 0; mt < 2; mt++)
        #pragma unroll
        for (int nt = 0; nt < 6; nt++)
            #pragma unroll
            for (int r = 0; r < 4; r++) acc[mt][nt][r] = 0.f;

    load_stage(0, 0);

    const int NK = D_ / 64;     // 16
    for (int kt = 0; kt < NK; kt++) {
        if (kt + 1 < NK) { load_stage((kt + 1) & 1, (kt + 1) * 64); CP_WAIT(1); }
        else             { CP_WAIT(0); }
        __syncthreads();

        uint32_t stage = sb + (kt & 1) * STAGE_B;
        #pragma unroll
        for (int kk = 0; kk < 4; kk++) {
            uint32_t ko = kk * 32;              // 16 halves per k-step
            uint32_t ah[2][4];
            #pragma unroll
            for (int mt = 0; mt < 2; mt++)
                ldsm4(ah[mt], stage + a_off + mt * (16 * TILE_PITCH) + ko);
            uint32_t bh[3][4];
            #pragma unroll
            for (int ng = 0; ng < 3; ng++)
                ldsm4(bh[ng], stage + T_B0 + b_off + ng * (16 * TILE_PITCH) + ko);
            #pragma unroll
            for (int mt = 0; mt < 2; mt++)
                #pragma unroll
                for (int ng = 0; ng < 3; ng++)
                    #pragma unroll
                    for (int hf = 0; hf < 2; hf++)
                        mma16816(acc[mt][ng * 2 + hf], ah[mt], &bh[ng][hf * 2]);
        }
        __syncthreads();
    }

    // epilogue: per-fragment qk(fp32) vs v(fp16) routing; boundary 512 is frag-aligned
    #pragma unroll
    for (int mt = 0; mt < 2; mt++) {
        int rbase = row0 + wr * 32 + mt * 16 + (lane >> 2);
        #pragma unroll
        for (int nt = 0; nt < 6; nt++) {
            int colg = col0 + wc * 48 + nt * 8 + (lane & 3) * 2;
            if (colg < QKW_) {
                *(float2*)(g_qk + (size_t)rbase * QKW_ + colg) =
                    make_float2(acc[mt][nt][0], acc[mt][nt][1]);
                *(float2*)(g_qk + (size_t)(rbase + 8) * QKW_ + colg) =
                    make_float2(acc[mt][nt][2], acc[mt][nt][3]);
            } else {
                int col = colg - QKW_;
                uint32_t p0, p1;
                CVT2PKH(p0, acc[mt][nt][0], acc[mt][nt][1]);
                CVT2PKH(p1, acc[mt][nt][2], acc[mt][nt][3]);
                *(uint32_t*)(g_vh + (size_t)rbase * D_ + col)       = p0;
                *(uint32_t*)(g_vh + (size_t)(rbase + 8) * D_ + col) = p1;
            }
        }
    }
}

// ---------------- L2 normalize + emit fp16 q (scaled), k --------------------
__global__ __launch_bounds__(256) void normalize_qk()
{
    int n = blockIdx.x;
    int b = n >> 11, nn = n & 2047;
    const float* p = g_qk + (size_t)n * QKW_;
    int t = threadIdx.x;
    float qv = p[t], kv = p[RANK_ + t];
    float qs = qv*qv, ks = kv*kv;
    #pragma unroll
    for (int o = 16; o; o >>= 1) {
        qs += __shfl_xor_sync(0xffffffffu, qs, o);
        ks += __shfl_xor_sync(0xffffffffu, ks, o);
    }
    __shared__ float sq[8], sk[8];
    if ((t & 31) == 0) { sq[t>>5] = qs; sk[t>>5] = ks; }
    __syncthreads();
    float qn = 0.f, kn = 0.f;
    #pragma unroll
    for (int w = 0; w < 8; w++) { qn += sq[w]; kn += sk[w]; }
    float qo = qv / fmaxf(sqrtf(qn), 1e-6f) * SCALE_;
    float ko = kv / fmaxf(sqrtf(kn), 1e-6f);

    int h = t >> 4, c = t & 15;
    size_t dst = ((size_t)(b*HEADS_ + h) * N_ + nn) * HS_ + c;
    g_q16[dst] = __float2half_rn(qo);
    g_k16[dst] = __float2half_rn(ko);
}

// ---------------- tensor-core causal flash attention ------------------------
// Q, K, V, P all single fp16 (scores tiny; errors average out).
#define SQ_   0
#define SST_  6144
#define STG_  12288
#define SKH_  0
#define SVH_  3072
#define FLASH_SMEM 30720    // 6144 + 2*12288

__global__ __launch_bounds__(256, 2) void flash_tc(float* __restrict__ out)
{
    extern __shared__ __align__(128) char smem[];
    const uint32_t sb = smem_u32(smem);
    const int tid = threadIdx.x, lane = tid & 31, wid = tid >> 5;
    const int qt = gridDim.x - 1 - blockIdx.x;
    const int h = blockIdx.y, b = blockIdx.z;
    const int q0 = qt * 128;
    const size_t bh = (size_t)(b*HEADS_ + h) * N_;
    const size_t vb = (size_t)b * N_;

    {   // Q: 128 rows x 2 chunks = 256
        int row = tid >> 1, c = tid & 1;
        cp_async16(sb + SQ_ + row * 48 + c * 16,
                   g_q16 + (bh + q0 + row) * HS_ + c * 8);
    }
    CP_COMMIT();

    auto load_kv = [&](int s, int ktile) {
        uint32_t st = sb + SST_ + s * STG_;
        int j0 = ktile * 64;
        if (tid < 128) {   // K: 64 rows x 2 chunks
            int c = tid & 1, row = tid >> 1;
            cp_async16(st + SKH_ + row * 48 + c * 16,
                       g_k16 + (bh + j0 + row) * HS_ + c * 8);
        }
        #pragma unroll
        for (int it = 0; it < 2; it++) {   // V: 64 rows x 8 chunks = 512
            int idx = tid + it * 256;
            int c = idx & 7, row = idx >> 3;
            cp_async16(st + SVH_ + row * 144 + c * 16,
                       g_vh + (vb + j0 + row) * D_ + h * DH_ + c * 8);
        }
        CP_COMMIT();
    };

    load_kv(0, 0);

    uint32_t qa[4];
    float yacc[8][4];
    #pragma unroll
    for (int nt = 0; nt < 8; nt++)
        #pragma unroll
        for (int r = 0; r < 4; r++) yacc[nt][r] = 0.f;
    float lsum0 = 0.f, lsum1 = 0.f;

    const int r0g = q0 + wid * 16 + (lane >> 2);
    const int r1g = r0g + 8;
    const int nkt = 2 * qt + 2;

    for (int kt = 0; kt < nkt; kt++) {
        if (kt + 1 < nkt) { load_kv((kt + 1) & 1, kt + 1); CP_WAIT(1); }
        else              { CP_WAIT(0); }
        __syncthreads();

        if (kt == 0) {
            uint32_t qoff = (uint32_t)((wid * 16 + (lane & 15)) * 48 + ((lane >> 4) << 4));
            ldsm4(qa, sb + SQ_ + qoff);
        }

        uint32_t st = sb + SST_ + (kt & 1) * STG_;
        uint32_t pah[4][4];

        const uint32_t koff = (uint32_t)((((lane >> 4) << 3) + (lane & 7)) * 48
                                         + (((lane >> 3) & 1) << 4));
        #pragma unroll
        for (int ntp = 0; ntp < 4; ntp++) {
            uint32_t khr[4];
            ldsm4(khr, st + SKH_ + koff + ntp * (16 * 48));
            float s0[4] = {0,0,0,0}, s1[4] = {0,0,0,0};
            mma16816(s0, qa, &khr[0]);
            mma16816(s1, qa, &khr[2]);

            #pragma unroll
            for (int hf = 0; hf < 2; hf++) {
                float* s = hf ? s1 : s0;
                int nt = ntp * 2 + hf;
                int c0 = kt * 64 + nt * 8 + 2 * (lane & 3);
                float p0 = (c0     <= r0g) ? exp_poly(s[0]) : 0.f;
                float p1 = (c0 + 1 <= r0g) ? exp_poly(s[1]) : 0.f;
                float p2 = (c0     <= r1g) ? exp_poly(s[2]) : 0.f;
                float p3 = (c0 + 1 <= r1g) ? exp_poly(s[3]) : 0.f;
                lsum0 += p0 + p1;
                lsum1 += p2 + p3;
                uint32_t hh01, hh23;
                CVT2PKH(hh01, p0, p1);
                CVT2PKH(hh23, p2, p3);
                int ks = nt >> 1, sl = (nt & 1) * 2;
                pah[ks][sl]     = hh01;
                pah[ks][sl + 1] = hh23;
            }
        }

        const uint32_t voff = (uint32_t)(((((lane >> 3) & 1) << 3) + (lane & 7)) * 144
                                         + ((lane >> 4) << 4));
        #pragma unroll
        for (int ks = 0; ks < 4; ks++) {
            #pragma unroll
            for (int dnp = 0; dnp < 4; dnp++) {
                uint32_t vh4[4];
                ldsm4t(vh4, st + SVH_ + voff + ks * (16 * 144) + dnp * 32);
                mma16816(yacc[2*dnp],     pah[ks], &vh4[0]);
                mma16816(yacc[2*dnp + 1], pah[ks], &vh4[2]);
            }
        }
        __syncthreads();
    }

    lsum0 += __shfl_xor_sync(0xffffffffu, lsum0, 1);
    lsum0 += __shfl_xor_sync(0xffffffffu, lsum0, 2);
    lsum1 += __shfl_xor_sync(0xffffffffu, lsum1, 1);
    lsum1 += __shfl_xor_sync(0xffffffffu, lsum1, 2);
    float inv0 = 1.f / fmaxf(lsum0, 1e-6f);
    float inv1 = 1.f / fmaxf(lsum1, 1e-6f);

    float* o0 = out + ((size_t)b * N_ + r0g) * D_ + h * DH_ + 2 * (lane & 3);
    #pragma unroll
    for (int nt = 0; nt < 8; nt++) {
        *(float2*)(o0 + nt * 8)           = make_float2(yacc[nt][0] * inv0, yacc[nt][1] * inv0);
        *(float2*)(o0 + nt * 8 + 8 * D_)  = make_float2(yacc[nt][2] * inv1, yacc[nt][3] * inv1);
    }
}

// ----------------------------------------------------------------------------
extern "C" void kernel_launch(void* const* d_in, const int* in_sizes, int n_in,
                              void* d_out, int out_size)
{
    const float* x   = (const float*)d_in[0];
    const float* Wqk = (const float*)d_in[2];
    const float* Wv  = (const float*)d_in[3];
    float* out = (float*)d_out;

    __half *x16, *wh;
    cudaGetSymbolAddress((void**)&x16, g_x16);
    cudaGetSymbolAddress((void**)&wh, g_wh);

    cudaFuncSetAttribute(gemm_fused, cudaFuncAttributeMaxDynamicSharedMemorySize, GEMM_SMEM);
    cudaFuncSetAttribute(flash_tc,   cudaFuncAttributeMaxDynamicSharedMemorySize, FLASH_SMEM);

    f32_to_f16_one<<<(MROWS*D_)/1024, 256>>>(x, x16);
    f32_to_f16_one<<<(QKW_*D_)/1024, 256>>>(Wqk, wh);
    f32_to_f16_one<<<(D_*D_)/1024, 256>>>(Wv, wh + (size_t)QKW_*D_);

    gemm_fused<<<dim3(CW_/NT_, MROWS/128), 256, GEMM_SMEM>>>(x16, wh);

    normalize_qk<<<MROWS, 256>>>();
    flash_tc<<<dim3(N_/128, HEADS_, B_), 256, FLASH_SMEM>>>(out);
}

// round 9
// speedup vs baseline: 8.6392x; 1.0303x over previous
#include <cuda_runtime.h>
#include <cuda_fp16.h>
#include <cstdint>
#include <math.h>

#define B_    2
#define N_    2048
#define D_    1024
#define RANK_ 256
#define HEADS_ 16
#define HS_   16
#define DH_   64
#define QKW_  512
#define CW_   1536           // merged GEMM output width (512 qk + 1024 v)
#define NT_   96             // GEMM N-tile
#define SCALE_ 0.25f
#define MROWS (B_*N_)        // 4096

// ---------------- device scratch (no allocation allowed) --------------------
__device__ __half g_qkh[MROWS*QKW_];      // fp16 qk pre-normalization
__device__ __half g_x16[MROWS*D_];        // x fp16
__device__ __half g_wh[CW_*D_];           // [Wqk;Wv] fp16
__device__ __half g_vh[MROWS*D_];         // v fp16
// q (scaled) and k fp16, [b,h,n,hs] layout
__device__ __half g_q16[B_*HEADS_*N_*HS_];
__device__ __half g_k16[B_*HEADS_*N_*HS_];

// ---------------- PTX helpers (sm_100-baseline safe) ------------------------
__device__ __forceinline__ uint32_t smem_u32(const void* p) {
    uint32_t a;
    asm("{ .reg .u64 t; cvta.to.shared.u64 t, %1; cvt.u32.u64 %0, t; }" : "=r"(a) : "l"(p));
    return a;
}
__device__ __forceinline__ void cp_async16(uint32_t dst, const void* src) {
    asm volatile("cp.async.cg.shared.global [%0], [%1], 16;" :: "r"(dst), "l"(src) : "memory");
}
#define CP_COMMIT() asm volatile("cp.async.commit_group;" ::: "memory")
#define CP_WAIT(n)  asm volatile("cp.async.wait_group %0;" :: "n"(n) : "memory")

__device__ __forceinline__ void ldsm4(uint32_t* r, uint32_t addr) {
    asm volatile("ldmatrix.sync.aligned.m8n8.x4.shared.b16 {%0,%1,%2,%3}, [%4];"
                 : "=r"(r[0]), "=r"(r[1]), "=r"(r[2]), "=r"(r[3]) : "r"(addr));
}
__device__ __forceinline__ void ldsm4t(uint32_t* r, uint32_t addr) {
    asm volatile("ldmatrix.sync.aligned.m8n8.x4.trans.shared.b16 {%0,%1,%2,%3}, [%4];"
                 : "=r"(r[0]), "=r"(r[1]), "=r"(r[2]), "=r"(r[3]) : "r"(addr));
}
__device__ __forceinline__ void mma16816(float* d, const uint32_t* a, const uint32_t* b) {
    asm volatile("mma.sync.aligned.m16n8k16.row.col.f32.f16.f16.f32 "
                 "{%0,%1,%2,%3}, {%4,%5,%6,%7}, {%8,%9}, {%0,%1,%2,%3};"
                 : "+f"(d[0]), "+f"(d[1]), "+f"(d[2]), "+f"(d[3])
                 : "r"(a[0]), "r"(a[1]), "r"(a[2]), "r"(a[3]), "r"(b[0]), "r"(b[1]));
}
// packed f32x2 -> f16x2 (lo arg in low half)
#define CVT2PKH(d, lo, hi) asm("cvt.rn.f16x2.f32 %0, %1, %2;" : "=r"(d) : "f"(hi), "f"(lo))

// exp(s) for |s| <= 0.26: Taylor-4, rel err < 1e-5
__device__ __forceinline__ float exp_poly(float s) {
    float p = fmaf(s, 1.f/24.f, 1.f/6.f);
    p = fmaf(s, p, 0.5f);
    p = fmaf(s, p, 1.f);
    p = fmaf(s, p, 1.f);
    return p;
}

// ---------------- merged fp32 -> fp16 conversion (x, Wqk, Wv) ---------------
// one block = 1024 elems. blocks [0,4096): x ; [4096,4608): Wqk ; [4608,5632): Wv
#define CVT_BLOCKS (4096 + 512 + 1024)
__global__ __launch_bounds__(256) void convert_all(const float* __restrict__ x,
                                                   const float* __restrict__ Wqk,
                                                   const float* __restrict__ Wv)
{
    int bid = blockIdx.x;
    const float* src;
    __half* dst;
    size_t off;
    if (bid < 4096)      { src = x;   dst = g_x16; off = (size_t)bid * 1024; }
    else if (bid < 4608) { src = Wqk; dst = g_wh;  off = (size_t)(bid - 4096) * 1024; }
    else                 { src = Wv;  dst = g_wh + (size_t)QKW_*D_; off = (size_t)(bid - 4608) * 1024; }
    size_t i = off + threadIdx.x * 4;
    float4 v = *(const float4*)(src + i);
    uint32_t h01, h23;
    CVT2PKH(h01, v.x, v.y);
    CVT2PKH(h23, v.z, v.w);
    *(uint2*)(dst + i) = make_uint2(h01, h23);
}

// ---------------- merged mma.sync fp16 GEMM ---------------------------------
// C[4096,1536] = x16 @ Wh^T.  cols <512 -> g_qkh fp16; cols >=512 -> g_vh fp16.
// 128(M) x 96(N) tile, BK=64, 12 warps (4M x 3N, each 32x32), occ 2 (24 warps/SM).
#define TILE_PITCH 144                  // 64 halves + 16B pad
#define AT_B   (128 * TILE_PITCH)       // 18432
#define BT_B   (NT_ * TILE_PITCH)       // 13824
#define T_B0   AT_B
#define STAGE_B (AT_B + BT_B)           // 32256
#define GEMM_SMEM (2 * STAGE_B)         // 64512

__global__ __launch_bounds__(384, 2) void gemm_fused(const __half* __restrict__ A16,
                                                     const __half* __restrict__ Wh)
{
    extern __shared__ __align__(128) char smem[];
    const uint32_t sb = smem_u32(smem);

    const int tid = threadIdx.x;
    const int lane = tid & 31, wid = tid >> 5;
    const int wr = wid & 3, wc = wid >> 2;           // 4M x 3N warp grid
    const int row0 = blockIdx.y * 128, col0 = blockIdx.x * NT_;

    const __half* pA = A16 + (size_t)row0 * D_;
    const __half* pB = Wh + (size_t)col0 * D_;
    const int lrow = tid >> 3, lc = tid & 7;         // 48 rows per 384-thread pass

    auto load_stage = [&](int s, int k0) {
        uint32_t dbase = sb + s * STAGE_B;
        #pragma unroll
        for (int it = 0; it < 3; it++) {             // A: 128 rows x 8 chunks
            int row = lrow + it * 48;
            if (it < 2 || row < 128)
                cp_async16(dbase + row * TILE_PITCH + lc * 16,
                           pA + (size_t)row * D_ + k0 + lc * 8);
        }
        #pragma unroll
        for (int it = 0; it < 2; it++) {             // B: 96 rows x 8 chunks
            int row = lrow + it * 48;
            cp_async16(dbase + T_B0 + row * TILE_PITCH + lc * 16,
                       pB + (size_t)row * D_ + k0 + lc * 8);
        }
        CP_COMMIT();
    };

    const uint32_t a_off = (uint32_t)((wr * 32 + (lane & 15)) * TILE_PITCH + ((lane >> 4) << 4));
    const uint32_t b_off = (uint32_t)((wc * 32 + (lane & 7) + ((lane >> 4) << 3)) * TILE_PITCH
                                      + (((lane >> 3) & 1) << 4));

    float acc[2][4][4];
    #pragma unroll
    for (int mt = 0; mt < 2; mt++)
        #pragma unroll
        for (int nt = 0; nt < 4; nt++)
            #pragma unroll
            for (int r = 0; r < 4; r++) acc[mt][nt][r] = 0.f;

    load_stage(0, 0);

    const int NK = D_ / 64;     // 16
    for (int kt = 0; kt < NK; kt++) {
        if (kt + 1 < NK) { load_stage((kt + 1) & 1, (kt + 1) * 64); CP_WAIT(1); }
        else             { CP_WAIT(0); }
        __syncthreads();

        uint32_t stage = sb + (kt & 1) * STAGE_B;
        #pragma unroll
        for (int kk = 0; kk < 4; kk++) {
            uint32_t ko = kk * 32;                  // 16 halves per k-step
            uint32_t ah[2][4];
            #pragma unroll
            for (int mt = 0; mt < 2; mt++)
                ldsm4(ah[mt], stage + a_off + mt * (16 * TILE_PITCH) + ko);
            uint32_t bh[2][4];
            #pragma unroll
            for (int ng = 0; ng < 2; ng++)
                ldsm4(bh[ng], stage + T_B0 + b_off + ng * (16 * TILE_PITCH) + ko);
            #pragma unroll
            for (int mt = 0; mt < 2; mt++)
                #pragma unroll
                for (int ng = 0; ng < 2; ng++)
                    #pragma unroll
                    for (int hf = 0; hf < 2; hf++)
                        mma16816(acc[mt][ng * 2 + hf], ah[mt], &bh[ng][hf * 2]);
        }
        __syncthreads();
    }

    // epilogue: fp16 everywhere; qk vs v routing per 8-col fragment
    #pragma unroll
    for (int mt = 0; mt < 2; mt++) {
        int rbase = row0 + wr * 32 + mt * 16 + (lane >> 2);
        #pragma unroll
        for (int nt = 0; nt < 4; nt++) {
            int colg = col0 + wc * 32 + nt * 8 + (lane & 3) * 2;
            uint32_t p0, p1;
            CVT2PKH(p0, acc[mt][nt][0], acc[mt][nt][1]);
            CVT2PKH(p1, acc[mt][nt][2], acc[mt][nt][3]);
            if (colg < QKW_) {
                *(uint32_t*)(g_qkh + (size_t)rbase * QKW_ + colg)       = p0;
                *(uint32_t*)(g_qkh + (size_t)(rbase + 8) * QKW_ + colg) = p1;
            } else {
                int col = colg - QKW_;
                *(uint32_t*)(g_vh + (size_t)rbase * D_ + col)       = p0;
                *(uint32_t*)(g_vh + (size_t)(rbase + 8) * D_ + col) = p1;
            }
        }
    }
}

// ---------------- L2 normalize + emit fp16 q (scaled), k --------------------
__global__ __launch_bounds__(256) void normalize_qk()
{
    int n = blockIdx.x;
    int b = n >> 11, nn = n & 2047;
    const __half* p = g_qkh + (size_t)n * QKW_;
    int t = threadIdx.x;
    float qv = __half2float(p[t]), kv = __half2float(p[RANK_ + t]);
    float qs = qv*qv, ks = kv*kv;
    #pragma unroll
    for (int o = 16; o; o >>= 1) {
        qs += __shfl_xor_sync(0xffffffffu, qs, o);
        ks += __shfl_xor_sync(0xffffffffu, ks, o);
    }
    __shared__ float sq[8], sk[8];
    if ((t & 31) == 0) { sq[t>>5] = qs; sk[t>>5] = ks; }
    __syncthreads();
    float qn = 0.f, kn = 0.f;
    #pragma unroll
    for (int w = 0; w < 8; w++) { qn += sq[w]; kn += sk[w]; }
    float qo = qv / fmaxf(sqrtf(qn), 1e-6f) * SCALE_;
    float ko = kv / fmaxf(sqrtf(kn), 1e-6f);

    int h = t >> 4, c = t & 15;
    size_t dst = ((size_t)(b*HEADS_ + h) * N_ + nn) * HS_ + c;
    g_q16[dst] = __float2half_rn(qo);
    g_k16[dst] = __float2half_rn(ko);
}

// ---------------- tensor-core causal flash attention ------------------------
// Q, K, V, P all single fp16 (scores tiny; errors average out).
#define SQ_   0
#define SST_  6144
#define STG_  12288
#define SKH_  0
#define SVH_  3072
#define FLASH_SMEM 30720    // 6144 + 2*12288

__global__ __launch_bounds__(256, 2) void flash_tc(float* __restrict__ out)
{
    extern __shared__ __align__(128) char smem[];
    const uint32_t sb = smem_u32(smem);
    const int tid = threadIdx.x, lane = tid & 31, wid = tid >> 5;
    const int qt = gridDim.x - 1 - blockIdx.x;
    const int h = blockIdx.y, b = blockIdx.z;
    const int q0 = qt * 128;
    const size_t bh = (size_t)(b*HEADS_ + h) * N_;
    const size_t vb = (size_t)b * N_;

    {   // Q: 128 rows x 2 chunks = 256
        int row = tid >> 1, c = tid & 1;
        cp_async16(sb + SQ_ + row * 48 + c * 16,
                   g_q16 + (bh + q0 + row) * HS_ + c * 8);
    }
    CP_COMMIT();

    auto load_kv = [&](int s, int ktile) {
        uint32_t st = sb + SST_ + s * STG_;
        int j0 = ktile * 64;
        if (tid < 128) {   // K: 64 rows x 2 chunks
            int c = tid & 1, row = tid >> 1;
            cp_async16(st + SKH_ + row * 48 + c * 16,
                       g_k16 + (bh + j0 + row) * HS_ + c * 8);
        }
        #pragma unroll
        for (int it = 0; it < 2; it++) {   // V: 64 rows x 8 chunks = 512
            int idx = tid + it * 256;
            int c = idx & 7, row = idx >> 3;
            cp_async16(st + SVH_ + row * 144 + c * 16,
                       g_vh + (vb + j0 + row) * D_ + h * DH_ + c * 8);
        }
        CP_COMMIT();
    };

    load_kv(0, 0);

    uint32_t qa[4];
    float yacc[8][4];
    #pragma unroll
    for (int nt = 0; nt < 8; nt++)
        #pragma unroll
        for (int r = 0; r < 4; r++) yacc[nt][r] = 0.f;
    float lsum0 = 0.f, lsum1 = 0.f;

    const int r0g = q0 + wid * 16 + (lane >> 2);
    const int r1g = r0g + 8;
    const int nkt = 2 * qt + 2;

    for (int kt = 0; kt < nkt; kt++) {
        if (kt + 1 < nkt) { load_kv((kt + 1) & 1, kt + 1); CP_WAIT(1); }
        else              { CP_WAIT(0); }
        __syncthreads();

        if (kt == 0) {
            uint32_t qoff = (uint32_t)((wid * 16 + (lane & 15)) * 48 + ((lane >> 4) << 4));
            ldsm4(qa, sb + SQ_ + qoff);
        }

        uint32_t st = sb + SST_ + (kt & 1) * STG_;
        uint32_t pah[4][4];

        const uint32_t koff = (uint32_t)((((lane >> 4) << 3) + (lane & 7)) * 48
                                         + (((lane >> 3) & 1) << 4));
        #pragma unroll
        for (int ntp = 0; ntp < 4; ntp++) {
            uint32_t khr[4];
            ldsm4(khr, st + SKH_ + koff + ntp * (16 * 48));
            float s0[4] = {0,0,0,0}, s1[4] = {0,0,0,0};
            mma16816(s0, qa, &khr[0]);
            mma16816(s1, qa, &khr[2]);

            #pragma unroll
            for (int hf = 0; hf < 2; hf++) {
                float* s = hf ? s1 : s0;
                int nt = ntp * 2 + hf;
                int c0 = kt * 64 + nt * 8 + 2 * (lane & 3);
                float p0 = (c0     <= r0g) ? exp_poly(s[0]) : 0.f;
                float p1 = (c0 + 1 <= r0g) ? exp_poly(s[1]) : 0.f;
                float p2 = (c0     <= r1g) ? exp_poly(s[2]) : 0.f;
                float p3 = (c0 + 1 <= r1g) ? exp_poly(s[3]) : 0.f;
                lsum0 += p0 + p1;
                lsum1 += p2 + p3;
                uint32_t hh01, hh23;
                CVT2PKH(hh01, p0, p1);
                CVT2PKH(hh23, p2, p3);
                int ks = nt >> 1, sl = (nt & 1) * 2;
                pah[ks][sl]     = hh01;
                pah[ks][sl + 1] = hh23;
            }
        }

        const uint32_t voff = (uint32_t)(((((lane >> 3) & 1) << 3) + (lane & 7)) * 144
                                         + ((lane >> 4) << 4));
        #pragma unroll
        for (int ks = 0; ks < 4; ks++) {
            #pragma unroll
            for (int dnp = 0; dnp < 4; dnp++) {
                uint32_t vh4[4];
                ldsm4t(vh4, st + SVH_ + voff + ks * (16 * 144) + dnp * 32);
                mma16816(yacc[2*dnp],     pah[ks], &vh4[0]);
                mma16816(yacc[2*dnp + 1], pah[ks], &vh4[2]);
            }
        }
        __syncthreads();
    }

    lsum0 += __shfl_xor_sync(0xffffffffu, lsum0, 1);
    lsum0 += __shfl_xor_sync(0xffffffffu, lsum0, 2);
    lsum1 += __shfl_xor_sync(0xffffffffu, lsum1, 1);
    lsum1 += __shfl_xor_sync(0xffffffffu, lsum1, 2);
    float inv0 = 1.f / fmaxf(lsum0, 1e-6f);
    float inv1 = 1.f / fmaxf(lsum1, 1e-6f);

    float* o0 = out + ((size_t)b * N_ + r0g) * D_ + h * DH_ + 2 * (lane & 3);
    #pragma unroll
    for (int nt = 0; nt < 8; nt++) {
        *(float2*)(o0 + nt * 8)           = make_float2(yacc[nt][0] * inv0, yacc[nt][1] * inv0);
        *(float2*)(o0 + nt * 8 + 8 * D_)  = make_float2(yacc[nt][2] * inv1, yacc[nt][3] * inv1);
    }
}

// ----------------------------------------------------------------------------
extern "C" void kernel_launch(void* const* d_in, const int* in_sizes, int n_in,
                              void* d_out, int out_size)
{
    const float* x   = (const float*)d_in[0];
    const float* Wqk = (const float*)d_in[2];
    const float* Wv  = (const float*)d_in[3];
    float* out = (float*)d_out;

    __half *x16, *wh;
    cudaGetSymbolAddress((void**)&x16, g_x16);
    cudaGetSymbolAddress((void**)&wh, g_wh);

    cudaFuncSetAttribute(gemm_fused, cudaFuncAttributeMaxDynamicSharedMemorySize, GEMM_SMEM);
    cudaFuncSetAttribute(flash_tc,   cudaFuncAttributeMaxDynamicSharedMemorySize, FLASH_SMEM);

    convert_all<<<CVT_BLOCKS, 256>>>(x, Wqk, Wv);

    gemm_fused<<<dim3(CW_/NT_, MROWS/128), 384, GEMM_SMEM>>>(x16, wh);

    normalize_qk<<<MROWS, 256>>>();
    flash_tc<<<dim3(N_/128, HEADS_, B_), 256, FLASH_SMEM>>>(out);
}